// round 11
// baseline (speedup 1.0000x reference)
#include <cuda_runtime.h>
#include <cuda_bf16.h>
#include <cstdint>

// Problem constants (fixed by the dataset)
#define E_CNT   800000
#define N_CNT   50000
#define NGR     16
#define NLAY    3
#define TE      128      // edges per k_mlp block

// ---------------- scratch (device globals; no allocations allowed) ----------
__device__ float g_ea[E_CNT * 64];            // edge features (per-layer output)
__device__ float g_hw[N_CNT * 128];           // hW = h @ W1top + b1 (per layer)
__device__ float g_hcur[N_CNT * 64];          // node features h
__device__ float g_hsum[N_CNT * 64];          // scatter-sum accumulator
__device__ int   g_cnt_node[N_CNT];           // in-degree per node
__device__ int   g_cnt_ng[NGR];               // nodes per graph
__device__ int   g_cnt_eg[NGR];               // edges per graph
__device__ float g_gnsum[(NLAY + 1) * NGR * 64];  // node pools (sums)
__device__ float g_gesum[(NLAY + 1) * NGR * 64];  // edge pools (sums)
// pre-split transposed weights: packed words {hi(bf16x2), lo(bf16x2)} per 2 k
__device__ uint2 g_W1t[NLAY * 128 * 64];      // [l][n(128)][kpair(64)]
__device__ uint2 g_W2t[NLAY * 64 * 64];       // [l][n(64)][kpair(64)]

// ---------------- PTX helpers ------------------------------------------------
__device__ __forceinline__ void red4(float* p, float4 v) {
    asm volatile("red.global.add.v4.f32 [%0], {%1,%2,%3,%4};"
                 :: "l"(p), "f"(v.x), "f"(v.y), "f"(v.z), "f"(v.w) : "memory");
}
__device__ __forceinline__ void red2(float* p, float2 v) {
    asm volatile("red.global.add.v2.f32 [%0], {%1,%2};"
                 :: "l"(p), "f"(v.x), "f"(v.y) : "memory");
}
__device__ __forceinline__ void red1(float* p, float v) {
    asm volatile("red.global.add.f32 [%0], %1;" :: "l"(p), "f"(v) : "memory");
}
// split two consecutive-k f32 values into packed bf16x2 {hi word, lo word}
__device__ __forceinline__ uint2 splitpack2(float a, float b) {
    __nv_bfloat16 ha = __float2bfloat16_rn(a);
    __nv_bfloat16 hb = __float2bfloat16_rn(b);
    __nv_bfloat16 la = __float2bfloat16_rn(a - __bfloat162float(ha));
    __nv_bfloat16 lb = __float2bfloat16_rn(b - __bfloat162float(hb));
    __nv_bfloat162 hv = __halves2bfloat162(ha, hb);   // .x = even k
    __nv_bfloat162 lv = __halves2bfloat162(la, lb);
    uint2 r;
    r.x = *reinterpret_cast<uint32_t*>(&hv);
    r.y = *reinterpret_cast<uint32_t*>(&lv);
    return r;
}
// m16n8k16 bf16 mma, row.col, f32 accumulate (fragment map per PTX ISA)
__device__ __forceinline__ void mma_bf16(float* d, uint32_t a0, uint32_t a1,
                                         uint32_t a2, uint32_t a3,
                                         uint32_t b0, uint32_t b1) {
    asm volatile(
        "mma.sync.aligned.m16n8k16.row.col.f32.bf16.bf16.f32 "
        "{%0,%1,%2,%3}, {%4,%5,%6,%7}, {%8,%9}, {%0,%1,%2,%3};"
        : "+f"(d[0]), "+f"(d[1]), "+f"(d[2]), "+f"(d[3])
        : "r"(a0), "r"(a1), "r"(a2), "r"(a3), "r"(b0), "r"(b1));
}

// ---------------- init: zero accumulators ------------------------------------
__global__ void k_init() {
    int t = blockIdx.x * blockDim.x + threadIdx.x;
    int stride = gridDim.x * blockDim.x;
    for (int i = t; i < N_CNT * 64; i += stride) g_hsum[i] = 0.f;
    for (int i = t; i < N_CNT; i += stride) g_cnt_node[i] = 0;
    for (int i = t; i < (NLAY + 1) * NGR * 64; i += stride) {
        g_gnsum[i] = 0.f;
        g_gesum[i] = 0.f;
    }
    for (int i = t; i < NGR; i += stride) { g_cnt_ng[i] = 0; g_cnt_eg[i] = 0; }
}

// ---------------- weight prep: transpose + bf16 hi/lo split (once) -----------
__global__ void k_wprep(const float* __restrict__ W1s, const float* __restrict__ W2s) {
    int t = blockIdx.x * blockDim.x + threadIdx.x;
    if (t < NLAY * 128 * 64) {                 // W1t: l, n(128), kp(64)
        int kp = t & 63, n = (t >> 6) & 127, l = t >> 13;
        float v0 = W1s[l * 16384 + (2 * kp) * 128 + n];
        float v1 = W1s[l * 16384 + (2 * kp + 1) * 128 + n];
        g_W1t[t] = splitpack2(v0, v1);
    } else {
        int u = t - NLAY * 128 * 64;
        if (u < NLAY * 64 * 64) {              // W2t: l, n(64), kp(64)
            int kp = u & 63, n = (u >> 6) & 63, l = u >> 12;
            float v0 = W2s[l * 8192 + (2 * kp) * 64 + n];
            float v1 = W2s[l * 8192 + (2 * kp + 1) * 64 + n];
            g_W2t[u] = splitpack2(v0, v1);
        }
    }
}

// ---------------- nodes-per-graph counts --------------------------------------
__global__ void k_node_cnt(const int* __restrict__ batch) {
    int t = blockIdx.x * blockDim.x + threadIdx.x;
    if (t < N_CNT) atomicAdd(&g_cnt_ng[batch[t]], 1);
}

// ---------------- layer-0 pooling + degree counts ------------------------------
__global__ void k_pool0(const float* __restrict__ edge_attr,
                        const int* __restrict__ eidx,
                        const int* __restrict__ eb) {
    __shared__ float stg[64 * 68];
    __shared__ float sP[128];
    __shared__ int sGBl[64];
    __shared__ int sColl[64];
    __shared__ int sCnt[2];
    int tid = threadIdx.x;
    int e0 = blockIdx.x * 64;
    if (tid < 128) sP[tid] = 0.f;
    if (tid < 64) { sGBl[tid] = eb[e0 + tid]; sColl[tid] = eidx[E_CNT + e0 + tid]; }
    if (tid < 2) sCnt[tid] = 0;
    __syncthreads();
    int gmin = sGBl[0];

    #pragma unroll
    for (int i = 0; i < 4; ++i) {
        int f = tid + i * 256;                 // 1024 = 64 edges x 16 col4
        int e = f >> 4, c4 = f & 15;
        float4 v = *(const float4*)(edge_attr + (size_t)(e0 + e) * 64 + c4 * 4);
        *(float4*)&stg[e * 68 + c4 * 4] = v;
        red4(&g_hsum[(size_t)sColl[e] * 64 + c4 * 4], v);
        if (c4 == 0) {
            atomicAdd(&g_cnt_node[sColl[e]], 1);
            int sl = sGBl[e] - gmin;
            if (sl < 2) atomicAdd(&sCnt[sl], 1);
            else atomicAdd(&g_cnt_eg[sGBl[e]], 1);
        }
    }
    __syncthreads();
    {
        int q = tid >> 6, c = tid & 63;
        float s0 = 0.f, s1 = 0.f;
        #pragma unroll
        for (int r = q * 16; r < q * 16 + 16; ++r) {
            float val = stg[r * 68 + c];
            int sl = sGBl[r] - gmin;
            if (sl == 0) s0 += val;
            else if (sl == 1) s1 += val;
            else red1(&g_gesum[sGBl[r] * 64 + c], val);
        }
        if (s0 != 0.f) atomicAdd(&sP[c], s0);
        if (s1 != 0.f) atomicAdd(&sP[64 + c], s1);
    }
    __syncthreads();
    if (tid < 128) {
        int sl = tid >> 6, c = tid & 63;
        int gg = gmin + sl;
        if (gg < NGR && sP[tid] != 0.f) red1(&g_gesum[gg * 64 + c], sP[tid]);
        if (tid < 2 && gmin + tid < NGR && sCnt[tid] > 0)
            atomicAdd(&g_cnt_eg[gmin + tid], sCnt[tid]);
    }
}

// ---------------- finalize h = h_sum/max(deg,1); pool to gn; zero h_sum --------
__global__ void k_finalize(int li, const int* __restrict__ batch) {
    __shared__ float sP[128];
    __shared__ int s_gmin;
    int tid = threadIdx.x;
    int v = blockIdx.x * 16 + (tid >> 4);
    int c4 = tid & 15;
    if (tid < 128) sP[tid] = 0.f;
    if (tid == 0) s_gmin = batch[blockIdx.x * 16];
    __syncthreads();

    float4 s = *(float4*)(g_hsum + (size_t)v * 64 + c4 * 4);
    float inv = 1.f / fmaxf((float)g_cnt_node[v], 1.f);
    float4 h = {s.x * inv, s.y * inv, s.z * inv, s.w * inv};
    *(float4*)(g_hcur + (size_t)v * 64 + c4 * 4) = h;
    float4 z = {0.f, 0.f, 0.f, 0.f};
    *(float4*)(g_hsum + (size_t)v * 64 + c4 * 4) = z;

    int gb = batch[v];
    int slot = gb - s_gmin;
    if (slot < 2) {
        atomicAdd(&sP[slot * 64 + c4 * 4 + 0], h.x);
        atomicAdd(&sP[slot * 64 + c4 * 4 + 1], h.y);
        atomicAdd(&sP[slot * 64 + c4 * 4 + 2], h.z);
        atomicAdd(&sP[slot * 64 + c4 * 4 + 3], h.w);
    } else {
        red4(&g_gnsum[li * NGR * 64 + gb * 64 + c4 * 4], h);
    }
    __syncthreads();
    if (tid < 32) {
        int sl = tid >> 4, cc = (tid & 15) * 4;
        int gg = s_gmin + sl;
        if (gg < NGR) {
            float4 p = *(float4*)&sP[sl * 64 + cc];
            if (p.x != 0.f || p.y != 0.f || p.z != 0.f || p.w != 0.f)
                red4(&g_gnsum[li * NGR * 64 + gg * 64 + cc], p);
        }
    }
}

// ---------------- node GEMM: hW = h @ W1top + b1 (per layer) -------------------
#define LDH36 36
__global__ void __launch_bounds__(256) k_hw(const float* __restrict__ b1, int layer) {
    __shared__ uint2 sH[128 * LDH36];
    int tid = threadIdx.x;
    int v0 = blockIdx.x * 128;

    #pragma unroll
    for (int i = 0; i < 8; ++i) {              // 2048 float4 = 128 rows x 16
        int f = tid + i * 256;
        int r = f >> 4, c4 = f & 15;
        int node = v0 + r;
        if (node >= N_CNT) node = N_CNT - 1;
        float4 x = *(const float4*)(g_hcur + (size_t)node * 64 + c4 * 4);
        uint2 w0 = splitpack2(x.x, x.y), w1 = splitpack2(x.z, x.w);
        uint4 pk = {w0.x, w0.y, w1.x, w1.y};
        *(uint4*)&sH[r * LDH36 + c4 * 2] = pk;
    }
    __syncthreads();

    const int wid = tid >> 5, lane = tid & 31;
    const int g = lane >> 2, t = lane & 3;
    const int r0 = (wid & 3) * 32, n0 = (wid >> 2) * 64;
    const uint2* pw1 = g_W1t + layer * 128 * 64;

    float acc[2][8][4];
    #pragma unroll
    for (int mi = 0; mi < 2; ++mi)
        #pragma unroll
        for (int ni = 0; ni < 8; ++ni)
            #pragma unroll
            for (int q = 0; q < 4; ++q) acc[mi][ni][q] = 0.f;

    #pragma unroll
    for (int ks = 0; ks < 4; ++ks) {
        int kw = ks * 8;
        uint32_t ahi[2][4], alo[2][4];
        #pragma unroll
        for (int mi = 0; mi < 2; ++mi) {
            const uint2* ap = sH + (r0 + 16 * mi + g) * LDH36 + kw + t;
            uint2 A0 = ap[0], A1 = ap[8 * LDH36], A2 = ap[4], A3 = ap[8 * LDH36 + 4];
            ahi[mi][0] = A0.x; ahi[mi][1] = A1.x; ahi[mi][2] = A2.x; ahi[mi][3] = A3.x;
            alo[mi][0] = A0.y; alo[mi][1] = A1.y; alo[mi][2] = A2.y; alo[mi][3] = A3.y;
        }
        #pragma unroll
        for (int ni = 0; ni < 8; ++ni) {
            const uint2* bp = pw1 + (n0 + 8 * ni + g) * 64 + kw + t;  // kpairs 0..31
            uint2 B0 = bp[0], B1 = bp[4];
            #pragma unroll
            for (int mi = 0; mi < 2; ++mi) {
                mma_bf16(acc[mi][ni], ahi[mi][0], ahi[mi][1], ahi[mi][2], ahi[mi][3], B0.x, B1.x);
                mma_bf16(acc[mi][ni], ahi[mi][0], ahi[mi][1], ahi[mi][2], ahi[mi][3], B0.y, B1.y);
                mma_bf16(acc[mi][ni], alo[mi][0], alo[mi][1], alo[mi][2], alo[mi][3], B0.x, B1.x);
            }
        }
    }
    #pragma unroll
    for (int mi = 0; mi < 2; ++mi) {
        int vl = v0 + r0 + 16 * mi + g, vh = vl + 8;
        #pragma unroll
        for (int ni = 0; ni < 8; ++ni) {
            int cc = n0 + 8 * ni + 2 * t;
            float ba = b1[cc], bb = b1[cc + 1];
            if (vl < N_CNT) {
                float2 o = {acc[mi][ni][0] + ba, acc[mi][ni][1] + bb};
                *(float2*)(g_hw + (size_t)vl * 128 + cc) = o;
            }
            if (vh < N_CNT) {
                float2 o = {acc[mi][ni][2] + ba, acc[mi][ni][3] + bb};
                *(float2*)(g_hw + (size_t)vh * 128 + cc) = o;
            }
        }
    }
}

// ---------------- fused edge MLP (bf16x3, register-fused GEMM1->GEMM2) --------
// 128 edges / 256 threads (8 warps). Each warp: 16 full rows. GEMM1 C-fragments
// ARE GEMM2 A-fragments (after in-register relu+hW+split) -> no hid smem
// round-trip, no second sync. B fragments from global (L1/L2-resident).
#define LDEA 36
#define SMEM_MLP_BYTES (128 * LDEA * 8 + 3 * 128 * 4 + 128 * 4)

__global__ void __launch_bounds__(256, 2)
k_mlp(const float* __restrict__ edge_attr,
      const int* __restrict__ eidx, const int* __restrict__ eb,
      const float* __restrict__ b2, int layer) {
    extern __shared__ char smem[];
    uint2* sEA = (uint2*)smem;                           // [128][36]
    int* sRow = (int*)(smem + 128 * LDEA * 8);
    int* sCol = sRow + 128;
    int* sGB  = sCol + 128;
    float* sGE = (float*)(sGB + 128);                    // [2][64]

    const float* ea_in = (layer == 0) ? edge_attr : g_ea;
    float* geout = g_gesum + (layer + 1) * NGR * 64;
    const uint2* pw1 = g_W1t + layer * 128 * 64;
    const uint2* pw2 = g_W2t + layer * 64 * 64;

    const int tid = threadIdx.x;
    const int e0 = blockIdx.x * TE;

    if (tid < 128) { sRow[tid] = eidx[e0 + tid]; sGE[tid] = 0.f; }
    else {
        int u = tid - 128;
        sCol[u] = eidx[E_CNT + e0 + u];
        sGB[u] = eb[e0 + u];
    }
    // gather ea (f32) + split -> sEA (stride 36 uint2)
    #pragma unroll
    for (int i = 0; i < 8; ++i) {
        int f = tid + i * 256;                 // 2048 float4 = 128 x 16
        int e = f >> 4, c4 = f & 15;
        float4 x = *(const float4*)(ea_in + (size_t)(e0 + e) * 64 + c4 * 4);
        uint2 w0 = splitpack2(x.x, x.y), w1 = splitpack2(x.z, x.w);
        uint4 pk = {w0.x, w0.y, w1.x, w1.y};
        *(uint4*)(sEA + e * LDEA + c4 * 2) = pk;
    }
    __syncthreads();

    const int wid = tid >> 5, lane = tid & 31;
    const int g = lane >> 2, t = lane & 3;
    const int r0 = wid * 16;                   // 16 rows per warp

    // ---- GEMM1: acc[16 rows][128 cols] = ea @ W1bot (K=64)
    float acc[16][4];
    #pragma unroll
    for (int ni = 0; ni < 16; ++ni)
        #pragma unroll
        for (int q = 0; q < 4; ++q) acc[ni][q] = 0.f;

    #pragma unroll
    for (int ks = 0; ks < 4; ++ks) {
        int kw = ks * 8;
        const uint2* ap = sEA + (r0 + g) * LDEA + kw + t;
        uint2 A0 = ap[0], A1 = ap[8 * LDEA], A2 = ap[4], A3 = ap[8 * LDEA + 4];
        #pragma unroll
        for (int ni = 0; ni < 16; ++ni) {
            const uint2* bp = pw1 + (8 * ni + g) * 64 + 32 + kw + t;  // kpairs 32..63
            uint2 B0 = bp[0], B1 = bp[4];
            mma_bf16(acc[ni], A0.x, A1.x, A2.x, A3.x, B0.x, B1.x);
            mma_bf16(acc[ni], A0.x, A1.x, A2.x, A3.x, B0.y, B1.y);
            mma_bf16(acc[ni], A0.y, A1.y, A2.y, A3.y, B0.x, B1.x);
        }
    }

    // in-register mid epilogue: hid = relu(acc + hW[row]); split -> A2 frags
    const int el = r0 + g, eh = r0 + 8 + g;    // this thread's two C rows
    const float* hwl = g_hw + (size_t)sRow[el] * 128;
    const float* hwh = g_hw + (size_t)sRow[eh] * 128;
    uint32_t ah0[16], al0[16], ah1[16], al1[16];
    #pragma unroll
    for (int ni = 0; ni < 16; ++ni) {
        int cc = 8 * ni + 2 * t;
        float2 hl = *(const float2*)(hwl + cc);
        float2 hh = *(const float2*)(hwh + cc);
        float v0 = fmaxf(acc[ni][0] + hl.x, 0.f);
        float v1 = fmaxf(acc[ni][1] + hl.y, 0.f);
        float v2 = fmaxf(acc[ni][2] + hh.x, 0.f);
        float v3 = fmaxf(acc[ni][3] + hh.y, 0.f);
        uint2 p0 = splitpack2(v0, v1);
        uint2 p1 = splitpack2(v2, v3);
        ah0[ni] = p0.x; al0[ni] = p0.y;        // row g,   kpair 4ni+t
        ah1[ni] = p1.x; al1[ni] = p1.y;        // row g+8, kpair 4ni+t
    }

    // ---- GEMM2: acc2[16 rows][64 cols] = hid @ W2 (K=128); A2 from registers
    float acc2[8][4];
    #pragma unroll
    for (int ni = 0; ni < 8; ++ni)
        #pragma unroll
        for (int q = 0; q < 4; ++q) acc2[ni][q] = 0.f;

    #pragma unroll
    for (int ks = 0; ks < 8; ++ks) {
        // k-group 16ks..16ks+15: a0 = kpair 8ks+t = frag of ni=2ks;
        // a2 = kpair 8ks+4+t = frag of ni=2ks+1
        uint32_t a0h = ah0[2 * ks], a2h = ah0[2 * ks + 1];
        uint32_t a1h = ah1[2 * ks], a3h = ah1[2 * ks + 1];
        uint32_t a0l = al0[2 * ks], a2l = al0[2 * ks + 1];
        uint32_t a1l = al1[2 * ks], a3l = al1[2 * ks + 1];
        #pragma unroll
        for (int ni = 0; ni < 8; ++ni) {
            const uint2* bp = pw2 + (8 * ni + g) * 64 + 8 * ks + t;
            uint2 B0 = bp[0], B1 = bp[4];
            mma_bf16(acc2[ni], a0h, a1h, a2h, a3h, B0.x, B1.x);
            mma_bf16(acc2[ni], a0h, a1h, a2h, a3h, B0.y, B1.y);
            mma_bf16(acc2[ni], a0l, a1l, a2l, a3l, B0.x, B1.x);
        }
    }

    // epilogue: +b2, store ea (f32), node scatter, graph pool (shfl-reduced)
    int gmin = sGB[0];
    int col0 = sCol[el], col1 = sCol[eh];
    int gb0 = sGB[el], gb1 = sGB[eh];
    int sl0 = gb0 - gmin, sl1 = gb1 - gmin;
    #pragma unroll
    for (int ni = 0; ni < 8; ++ni) {
        int cc = 8 * ni + 2 * t;
        float b2a = b2[cc], b2b = b2[cc + 1];
        float s0x = 0.f, s0y = 0.f, s1x = 0.f, s1y = 0.f;
        float2 lo = {acc2[ni][0] + b2a, acc2[ni][1] + b2b};
        float2 hi = {acc2[ni][2] + b2a, acc2[ni][3] + b2b};
        *(float2*)(g_ea + (size_t)(e0 + el) * 64 + cc) = lo;
        *(float2*)(g_ea + (size_t)(e0 + eh) * 64 + cc) = hi;
        red2(&g_hsum[(size_t)col0 * 64 + cc], lo);
        red2(&g_hsum[(size_t)col1 * 64 + cc], hi);
        if (sl0 == 0) { s0x += lo.x; s0y += lo.y; }
        else if (sl0 == 1) { s1x += lo.x; s1y += lo.y; }
        else red2(&geout[gb0 * 64 + cc], lo);
        if (sl1 == 0) { s0x += hi.x; s0y += hi.y; }
        else if (sl1 == 1) { s1x += hi.x; s1y += hi.y; }
        else red2(&geout[gb1 * 64 + cc], hi);
        #pragma unroll
        for (int off = 16; off >= 4; off >>= 1) {
            s0x += __shfl_xor_sync(0xffffffffu, s0x, off);
            s0y += __shfl_xor_sync(0xffffffffu, s0y, off);
            s1x += __shfl_xor_sync(0xffffffffu, s1x, off);
            s1y += __shfl_xor_sync(0xffffffffu, s1y, off);
        }
        if (lane < 4) {
            if (s0x != 0.f) atomicAdd(&sGE[cc], s0x);
            if (s0y != 0.f) atomicAdd(&sGE[cc + 1], s0y);
            if (s1x != 0.f) atomicAdd(&sGE[64 + cc], s1x);
            if (s1y != 0.f) atomicAdd(&sGE[64 + cc + 1], s1y);
        }
    }
    __syncthreads();
    if (tid < 128) {     // flush SMEM graph pool
        int sl = tid >> 6, c = tid & 63;
        int gg = sGB[0] + sl;
        if (gg < NGR && sGE[tid] != 0.f) red1(&geout[gg * 64 + c], sGE[tid]);
    }
}

// ---------------- output head: one block per graph ----------------------------
__global__ void k_head(const float* __restrict__ Wo1, const float* __restrict__ bo1,
                       const float* __restrict__ Wo2, const float* __restrict__ bo2,
                       const float* __restrict__ Wo3, const float* __restrict__ bo3,
                       float* __restrict__ out) {
    __shared__ float aa[512];
    __shared__ float s1[128];
    __shared__ float s2[128];
    int g = blockIdx.x;
    int tid = threadIdx.x;
    float ninv = 1.f / fmaxf((float)g_cnt_ng[g], 1.f);
    float einv = 1.f / fmaxf((float)g_cnt_eg[g], 1.f);
    for (int i = tid; i < 512; i += 128) {
        float v;
        if (i < 256) {
            v = g_gnsum[(i >> 6) * NGR * 64 + g * 64 + (i & 63)] * ninv;
            out[g * 256 + i] = v;
        } else {
            int c = i - 256;
            v = g_gesum[(c >> 6) * NGR * 64 + g * 64 + (c & 63)] * einv;
            out[4096 + g * 256 + c] = v;
        }
        aa[i] = v;
    }
    __syncthreads();
    {
        float s = bo1[tid];
        for (int k = 0; k < 512; ++k) s = fmaf(aa[k], Wo1[k * 128 + tid], s);
        s1[tid] = fmaxf(s, 0.f);
    }
    __syncthreads();
    {
        float s = bo2[tid];
        for (int k = 0; k < 128; ++k) s = fmaf(s1[k], Wo2[k * 128 + tid], s);
        s2[tid] = fmaxf(s, 0.f);
    }
    __syncthreads();
    if (tid < 32) {
        float s = bo3[tid];
        for (int k = 0; k < 128; ++k) s = fmaf(s2[k], Wo3[k * 32 + tid], s);
        out[8192 + g * 32 + tid] = s;
    }
}

// ---------------- launcher ----------------------------------------------------
extern "C" void kernel_launch(void* const* d_in, const int* in_sizes, int n_in,
                              void* d_out, int out_size) {
    const float* edge_attr = (const float*)d_in[1];
    const int*   eidx      = (const int*)d_in[3];
    const int*   batch     = (const int*)d_in[4];
    const int*   eb        = (const int*)d_in[5];
    const float* W1s       = (const float*)d_in[6];
    const float* b1s       = (const float*)d_in[7];
    const float* W2s       = (const float*)d_in[8];
    const float* b2s       = (const float*)d_in[9];
    const float* Wo1       = (const float*)d_in[10];
    const float* bo1       = (const float*)d_in[11];
    const float* Wo2       = (const float*)d_in[12];
    const float* bo2       = (const float*)d_in[13];
    const float* Wo3       = (const float*)d_in[14];
    const float* bo3       = (const float*)d_in[15];
    float* out = (float*)d_out;

    cudaFuncSetAttribute((const void*)k_mlp,
                         cudaFuncAttributeMaxDynamicSharedMemorySize,
                         SMEM_MLP_BYTES);

    k_init<<<2048, 256>>>();
    k_wprep<<<(NLAY * 128 * 64 + NLAY * 64 * 64 + 255) / 256, 256>>>(W1s, W2s);
    k_node_cnt<<<(N_CNT + 255) / 256, 256>>>(batch);
    k_pool0<<<E_CNT / 64, 256>>>(edge_attr, eidx, eb);
    k_finalize<<<N_CNT / 16, 256>>>(0, batch);

    for (int l = 0; l < NLAY; ++l) {
        k_hw<<<(N_CNT + 127) / 128, 256>>>(b1s + l * 128, l);
        k_mlp<<<E_CNT / TE, 256, SMEM_MLP_BYTES>>>(
            edge_attr, eidx, eb, b2s + l * 64, l);
        k_finalize<<<N_CNT / 16, 256>>>(l + 1, batch);
    }

    k_head<<<NGR, 128>>>(Wo1, bo1, Wo2, bo2, Wo3, bo3, out);
}

// round 12
// speedup vs baseline: 1.2567x; 1.2567x over previous
#include <cuda_runtime.h>
#include <cuda_bf16.h>
#include <cstdint>

// Problem constants (fixed by the dataset)
#define E_CNT   800000
#define N_CNT   50000
#define NGR     16
#define NLAY    3
#define TE      128      // edges per k_mlp block

// ---------------- scratch (device globals; no allocations allowed) ----------
__device__ float g_ea[E_CNT * 64];            // edge features (per-layer output)
__device__ float g_hw[N_CNT * 128];           // hW = h @ W1top + b1 (per layer)
__device__ float g_hsum[N_CNT * 64];          // scatter-sum accumulator
__device__ int   g_cnt_node[N_CNT];           // in-degree per node
__device__ int   g_cnt_ng[NGR];               // nodes per graph
__device__ int   g_cnt_eg[NGR];               // edges per graph
__device__ float g_gnsum[(NLAY + 1) * NGR * 64];  // node pools (sums)
__device__ float g_gesum[(NLAY + 1) * NGR * 64];  // edge pools (sums)
// pre-split transposed weights: packed words {hi(bf16x2), lo(bf16x2)} per 2 k
__device__ uint2 g_W1t[NLAY * 128 * 64];      // [l][n(128)][kpair(64)]
__device__ uint2 g_W2t[NLAY * 64 * 64];       // [l][n(64)][kpair(64)]

// ---------------- PTX helpers ------------------------------------------------
__device__ __forceinline__ void red4(float* p, float4 v) {
    asm volatile("red.global.add.v4.f32 [%0], {%1,%2,%3,%4};"
                 :: "l"(p), "f"(v.x), "f"(v.y), "f"(v.z), "f"(v.w) : "memory");
}
__device__ __forceinline__ void red2(float* p, float2 v) {
    asm volatile("red.global.add.v2.f32 [%0], {%1,%2};"
                 :: "l"(p), "f"(v.x), "f"(v.y) : "memory");
}
__device__ __forceinline__ void red1(float* p, float v) {
    asm volatile("red.global.add.f32 [%0], %1;" :: "l"(p), "f"(v) : "memory");
}
// split two consecutive-k f32 values into packed bf16x2 {hi word, lo word}
__device__ __forceinline__ uint2 splitpack2(float a, float b) {
    __nv_bfloat16 ha = __float2bfloat16_rn(a);
    __nv_bfloat16 hb = __float2bfloat16_rn(b);
    __nv_bfloat16 la = __float2bfloat16_rn(a - __bfloat162float(ha));
    __nv_bfloat16 lb = __float2bfloat16_rn(b - __bfloat162float(hb));
    __nv_bfloat162 hv = __halves2bfloat162(ha, hb);   // .x = even k
    __nv_bfloat162 lv = __halves2bfloat162(la, lb);
    uint2 r;
    r.x = *reinterpret_cast<uint32_t*>(&hv);
    r.y = *reinterpret_cast<uint32_t*>(&lv);
    return r;
}
// m16n8k16 bf16 mma, row.col, f32 accumulate (fragment map per PTX ISA)
__device__ __forceinline__ void mma_bf16(float* d, uint32_t a0, uint32_t a1,
                                         uint32_t a2, uint32_t a3,
                                         uint32_t b0, uint32_t b1) {
    asm volatile(
        "mma.sync.aligned.m16n8k16.row.col.f32.bf16.bf16.f32 "
        "{%0,%1,%2,%3}, {%4,%5,%6,%7}, {%8,%9}, {%0,%1,%2,%3};"
        : "+f"(d[0]), "+f"(d[1]), "+f"(d[2]), "+f"(d[3])
        : "r"(a0), "r"(a1), "r"(a2), "r"(a3), "r"(b0), "r"(b1));
}

// ---------------- init: zero accumulators ------------------------------------
__global__ void k_init() {
    int t = blockIdx.x * blockDim.x + threadIdx.x;
    int stride = gridDim.x * blockDim.x;
    for (int i = t; i < N_CNT * 64; i += stride) g_hsum[i] = 0.f;
    for (int i = t; i < N_CNT; i += stride) g_cnt_node[i] = 0;
    for (int i = t; i < (NLAY + 1) * NGR * 64; i += stride) {
        g_gnsum[i] = 0.f;
        g_gesum[i] = 0.f;
    }
    for (int i = t; i < NGR; i += stride) { g_cnt_ng[i] = 0; g_cnt_eg[i] = 0; }
}

// ---------------- weight prep: transpose + bf16 hi/lo split (once) -----------
__global__ void k_wprep(const float* __restrict__ W1s, const float* __restrict__ W2s) {
    int t = blockIdx.x * blockDim.x + threadIdx.x;
    if (t < NLAY * 128 * 64) {                 // W1t: l, n(128), kp(64)
        int kp = t & 63, n = (t >> 6) & 127, l = t >> 13;
        float v0 = W1s[l * 16384 + (2 * kp) * 128 + n];
        float v1 = W1s[l * 16384 + (2 * kp + 1) * 128 + n];
        g_W1t[t] = splitpack2(v0, v1);
    } else {
        int u = t - NLAY * 128 * 64;
        if (u < NLAY * 64 * 64) {              // W2t: l, n(64), kp(64)
            int kp = u & 63, n = (u >> 6) & 63, l = u >> 12;
            float v0 = W2s[l * 8192 + (2 * kp) * 64 + n];
            float v1 = W2s[l * 8192 + (2 * kp + 1) * 64 + n];
            g_W2t[u] = splitpack2(v0, v1);
        }
    }
}

// ---------------- nodes-per-graph counts --------------------------------------
__global__ void k_node_cnt(const int* __restrict__ batch) {
    int t = blockIdx.x * blockDim.x + threadIdx.x;
    if (t < N_CNT) atomicAdd(&g_cnt_ng[batch[t]], 1);
}

// ---------------- layer-0 pooling + degree counts ------------------------------
__global__ void k_pool0(const float* __restrict__ edge_attr,
                        const int* __restrict__ eidx,
                        const int* __restrict__ eb) {
    __shared__ float stg[64 * 68];
    __shared__ float sP[128];
    __shared__ int sGBl[64];
    __shared__ int sColl[64];
    __shared__ int sCnt[2];
    int tid = threadIdx.x;
    int e0 = blockIdx.x * 64;
    if (tid < 128) sP[tid] = 0.f;
    if (tid < 64) { sGBl[tid] = eb[e0 + tid]; sColl[tid] = eidx[E_CNT + e0 + tid]; }
    if (tid < 2) sCnt[tid] = 0;
    __syncthreads();
    int gmin = sGBl[0];

    #pragma unroll
    for (int i = 0; i < 4; ++i) {
        int f = tid + i * 256;                 // 1024 = 64 edges x 16 col4
        int e = f >> 4, c4 = f & 15;
        float4 v = *(const float4*)(edge_attr + (size_t)(e0 + e) * 64 + c4 * 4);
        *(float4*)&stg[e * 68 + c4 * 4] = v;
        red4(&g_hsum[(size_t)sColl[e] * 64 + c4 * 4], v);
        if (c4 == 0) {
            atomicAdd(&g_cnt_node[sColl[e]], 1);
            int sl = sGBl[e] - gmin;
            if (sl < 2) atomicAdd(&sCnt[sl], 1);
            else atomicAdd(&g_cnt_eg[sGBl[e]], 1);
        }
    }
    __syncthreads();
    {
        int q = tid >> 6, c = tid & 63;
        float s0 = 0.f, s1 = 0.f;
        #pragma unroll
        for (int r = q * 16; r < q * 16 + 16; ++r) {
            float val = stg[r * 68 + c];
            int sl = sGBl[r] - gmin;
            if (sl == 0) s0 += val;
            else if (sl == 1) s1 += val;
            else red1(&g_gesum[sGBl[r] * 64 + c], val);
        }
        if (s0 != 0.f) atomicAdd(&sP[c], s0);
        if (s1 != 0.f) atomicAdd(&sP[64 + c], s1);
    }
    __syncthreads();
    if (tid < 128) {
        int sl = tid >> 6, c = tid & 63;
        int gg = gmin + sl;
        if (gg < NGR && sP[tid] != 0.f) red1(&g_gesum[gg * 64 + c], sP[tid]);
        if (tid < 2 && gmin + tid < NGR && sCnt[tid] > 0)
            atomicAdd(&g_cnt_eg[gmin + tid], sCnt[tid]);
    }
}

// ---------------- fused finalize + node GEMM (hW = h @ W1top + b1) -------------
// 128 nodes / 256 threads. Computes h = hsum/deg, pools to gnsum, zeros hsum,
// splits h, and (if do_hw) computes hW for the next k_mlp. No g_hcur.
#define LDH36 36
__global__ void __launch_bounds__(256)
k_finhw(int li, const int* __restrict__ batch, const float* __restrict__ b1,
        int layer, int do_hw) {
    __shared__ uint2 sH[128 * LDH36];
    __shared__ float sP[128];
    __shared__ int s_gmin;
    int tid = threadIdx.x;
    int v0 = blockIdx.x * 128;
    if (tid < 128) sP[tid] = 0.f;
    if (tid == 0) s_gmin = batch[v0 < N_CNT ? v0 : (N_CNT - 1)];
    __syncthreads();
    int gmin = s_gmin;

    #pragma unroll
    for (int i = 0; i < 8; ++i) {
        int f = tid + i * 256;                 // 2048 = 128 rows x 16 col4
        int r = f >> 4, c4 = f & 15;
        int node = v0 + r;
        if (node < N_CNT) {
            float4 s = *(float4*)(g_hsum + (size_t)node * 64 + c4 * 4);
            float inv = 1.f / fmaxf((float)g_cnt_node[node], 1.f);
            float4 h = {s.x * inv, s.y * inv, s.z * inv, s.w * inv};
            float4 z = {0.f, 0.f, 0.f, 0.f};
            *(float4*)(g_hsum + (size_t)node * 64 + c4 * 4) = z;
            int gb = batch[node];
            int sl = gb - gmin;
            if (sl < 2) {
                atomicAdd(&sP[sl * 64 + c4 * 4 + 0], h.x);
                atomicAdd(&sP[sl * 64 + c4 * 4 + 1], h.y);
                atomicAdd(&sP[sl * 64 + c4 * 4 + 2], h.z);
                atomicAdd(&sP[sl * 64 + c4 * 4 + 3], h.w);
            } else {
                red4(&g_gnsum[li * NGR * 64 + gb * 64 + c4 * 4], h);
            }
            uint2 w0 = splitpack2(h.x, h.y), w1 = splitpack2(h.z, h.w);
            uint4 pk = {w0.x, w0.y, w1.x, w1.y};
            *(uint4*)&sH[r * LDH36 + c4 * 2] = pk;
        } else {
            uint4 pk = {0u, 0u, 0u, 0u};
            *(uint4*)&sH[r * LDH36 + c4 * 2] = pk;
        }
    }
    __syncthreads();
    if (tid < 128) {
        int sl = tid >> 6, c = tid & 63;
        int gg = gmin + sl;
        if (gg < NGR && sP[tid] != 0.f)
            red1(&g_gnsum[li * NGR * 64 + gg * 64 + c], sP[tid]);
    }
    if (!do_hw) return;

    const int wid = tid >> 5, lane = tid & 31;
    const int g = lane >> 2, t = lane & 3;
    const int r0 = (wid & 3) * 32, n0 = (wid >> 2) * 64;
    const uint2* pw1 = g_W1t + layer * 128 * 64;

    float acc[2][8][4];
    #pragma unroll
    for (int mi = 0; mi < 2; ++mi)
        #pragma unroll
        for (int ni = 0; ni < 8; ++ni)
            #pragma unroll
            for (int q = 0; q < 4; ++q) acc[mi][ni][q] = 0.f;

    #pragma unroll
    for (int ks = 0; ks < 4; ++ks) {
        int kw = ks * 8;
        uint32_t ahi[2][4], alo[2][4];
        #pragma unroll
        for (int mi = 0; mi < 2; ++mi) {
            const uint2* ap = sH + (r0 + 16 * mi + g) * LDH36 + kw + t;
            uint2 A0 = ap[0], A1 = ap[8 * LDH36], A2 = ap[4], A3 = ap[8 * LDH36 + 4];
            ahi[mi][0] = A0.x; ahi[mi][1] = A1.x; ahi[mi][2] = A2.x; ahi[mi][3] = A3.x;
            alo[mi][0] = A0.y; alo[mi][1] = A1.y; alo[mi][2] = A2.y; alo[mi][3] = A3.y;
        }
        #pragma unroll
        for (int ni = 0; ni < 8; ++ni) {
            const uint2* bp = pw1 + (n0 + 8 * ni + g) * 64 + kw + t;  // kpairs 0..31
            uint2 B0 = bp[0], B1 = bp[4];
            #pragma unroll
            for (int mi = 0; mi < 2; ++mi) {
                mma_bf16(acc[mi][ni], ahi[mi][0], ahi[mi][1], ahi[mi][2], ahi[mi][3], B0.x, B1.x);
                mma_bf16(acc[mi][ni], ahi[mi][0], ahi[mi][1], ahi[mi][2], ahi[mi][3], B0.y, B1.y);
                mma_bf16(acc[mi][ni], alo[mi][0], alo[mi][1], alo[mi][2], alo[mi][3], B0.x, B1.x);
            }
        }
    }
    #pragma unroll
    for (int mi = 0; mi < 2; ++mi) {
        int vl = v0 + r0 + 16 * mi + g, vh = vl + 8;
        #pragma unroll
        for (int ni = 0; ni < 8; ++ni) {
            int cc = n0 + 8 * ni + 2 * t;
            float ba = b1[cc], bb = b1[cc + 1];
            if (vl < N_CNT) {
                float2 o = {acc[mi][ni][0] + ba, acc[mi][ni][1] + bb};
                *(float2*)(g_hw + (size_t)vl * 128 + cc) = o;
            }
            if (vh < N_CNT) {
                float2 o = {acc[mi][ni][2] + ba, acc[mi][ni][3] + bb};
                *(float2*)(g_hw + (size_t)vh * 128 + cc) = o;
            }
        }
    }
}

// ---------------- fused edge MLP (bf16x3, K-split, global W) + scatter ---------
// 128 edges / 256 threads, occ 2 (~108.5KB smem). R6 engine exactly.
#define LDEA 36
#define LDHD 68
#define SMEM_MLP_BYTES (128 * LDEA * 8 + 128 * LDHD * 8 + 3 * 128 * 4 + 128 * 4)

__global__ void __launch_bounds__(256, 2)
k_mlp(const float* __restrict__ edge_attr,
      const int* __restrict__ eidx, const int* __restrict__ eb,
      const float* __restrict__ b2, int layer) {
    extern __shared__ char smem[];
    uint2* sEA  = (uint2*)smem;                          // [128][36]
    uint2* sHID = (uint2*)(smem + 128 * LDEA * 8);       // [128][68]
    int* sRow = (int*)(smem + 128 * LDEA * 8 + 128 * LDHD * 8);
    int* sCol = sRow + 128;
    int* sGB  = sCol + 128;
    float* sGE = (float*)(sGB + 128);                    // [2][64]

    const float* ea_in = (layer == 0) ? edge_attr : g_ea;
    float* geout = g_gesum + (layer + 1) * NGR * 64;
    const uint2* pw1 = g_W1t + layer * 128 * 64;
    const uint2* pw2 = g_W2t + layer * 64 * 64;

    const int tid = threadIdx.x;
    const int e0 = blockIdx.x * TE;

    if (tid < 128) { sRow[tid] = eidx[e0 + tid]; sGE[tid] = 0.f; }
    else {
        int u = tid - 128;
        sCol[u] = eidx[E_CNT + e0 + u];
        sGB[u] = eb[e0 + u];
    }
    // gather ea (f32) + split -> sEA (stride 36 uint2)
    #pragma unroll
    for (int i = 0; i < 8; ++i) {
        int f = tid + i * 256;                 // 2048 float4 = 128 x 16
        int e = f >> 4, c4 = f & 15;
        float4 x = *(const float4*)(ea_in + (size_t)(e0 + e) * 64 + c4 * 4);
        uint2 w0 = splitpack2(x.x, x.y), w1 = splitpack2(x.z, x.w);
        uint4 pk = {w0.x, w0.y, w1.x, w1.y};
        *(uint4*)(sEA + e * LDEA + c4 * 2) = pk;
    }
    __syncthreads();

    const int wid = tid >> 5, lane = tid & 31;
    const int g = lane >> 2, t = lane & 3;
    const int r0 = (wid & 3) * 32;

    // ---- GEMM1-edge: acc = ea @ W1bot (K=64), tiles 32x64, B from global
    const int n0 = (wid >> 2) * 64;
    float acc[2][8][4];
    #pragma unroll
    for (int mi = 0; mi < 2; ++mi)
        #pragma unroll
        for (int ni = 0; ni < 8; ++ni)
            #pragma unroll
            for (int q = 0; q < 4; ++q) acc[mi][ni][q] = 0.f;

    #pragma unroll
    for (int ks = 0; ks < 4; ++ks) {
        int kw = ks * 8;
        uint32_t ahi[2][4], alo[2][4];
        #pragma unroll
        for (int mi = 0; mi < 2; ++mi) {
            const uint2* ap = sEA + (r0 + 16 * mi + g) * LDEA + kw + t;
            uint2 A0 = ap[0], A1 = ap[8 * LDEA], A2 = ap[4], A3 = ap[8 * LDEA + 4];
            ahi[mi][0] = A0.x; ahi[mi][1] = A1.x; ahi[mi][2] = A2.x; ahi[mi][3] = A3.x;
            alo[mi][0] = A0.y; alo[mi][1] = A1.y; alo[mi][2] = A2.y; alo[mi][3] = A3.y;
        }
        #pragma unroll
        for (int ni = 0; ni < 8; ++ni) {
            const uint2* bp = pw1 + (n0 + 8 * ni + g) * 64 + 32 + kw + t;  // kpairs 32..63
            uint2 B0 = bp[0], B1 = bp[4];
            #pragma unroll
            for (int mi = 0; mi < 2; ++mi) {
                mma_bf16(acc[mi][ni], ahi[mi][0], ahi[mi][1], ahi[mi][2], ahi[mi][3], B0.x, B1.x);
                mma_bf16(acc[mi][ni], ahi[mi][0], ahi[mi][1], ahi[mi][2], ahi[mi][3], B0.y, B1.y);
                mma_bf16(acc[mi][ni], alo[mi][0], alo[mi][1], alo[mi][2], alo[mi][3], B0.x, B1.x);
            }
        }
    }

    // mid epilogue: hid = relu(acc + hW[row]); split -> sHID
    #pragma unroll
    for (int mi = 0; mi < 2; ++mi) {
        int el = r0 + 16 * mi + g, eh = el + 8;
        const float* hwl = g_hw + (size_t)sRow[el] * 128;
        const float* hwh = g_hw + (size_t)sRow[eh] * 128;
        #pragma unroll
        for (int ni = 0; ni < 8; ++ni) {
            int cc = n0 + 8 * ni + 2 * t;
            float2 hl = *(const float2*)(hwl + cc);
            float2 hh = *(const float2*)(hwh + cc);
            float v0 = fmaxf(acc[mi][ni][0] + hl.x, 0.f);
            float v1 = fmaxf(acc[mi][ni][1] + hl.y, 0.f);
            float v2 = fmaxf(acc[mi][ni][2] + hh.x, 0.f);
            float v3 = fmaxf(acc[mi][ni][3] + hh.y, 0.f);
            int wd = (n0 >> 1) + 4 * ni + t;
            sHID[el * LDHD + wd] = splitpack2(v0, v1);
            sHID[eh * LDHD + wd] = splitpack2(v2, v3);
        }
    }
    __syncthreads();

    // ---- GEMM2: out = hid @ W2 (K=128), tiles 32x32, B from global
    const int n2 = (wid >> 2) * 32;
    float acc2[2][4][4];
    #pragma unroll
    for (int mi = 0; mi < 2; ++mi)
        #pragma unroll
        for (int ni = 0; ni < 4; ++ni)
            #pragma unroll
            for (int q = 0; q < 4; ++q) acc2[mi][ni][q] = 0.f;

    #pragma unroll
    for (int ks = 0; ks < 8; ++ks) {
        int kw = ks * 8;
        uint32_t ahi[2][4], alo[2][4];
        #pragma unroll
        for (int mi = 0; mi < 2; ++mi) {
            const uint2* ap = sHID + (r0 + 16 * mi + g) * LDHD + kw + t;
            uint2 A0 = ap[0], A1 = ap[8 * LDHD], A2 = ap[4], A3 = ap[8 * LDHD + 4];
            ahi[mi][0] = A0.x; ahi[mi][1] = A1.x; ahi[mi][2] = A2.x; ahi[mi][3] = A3.x;
            alo[mi][0] = A0.y; alo[mi][1] = A1.y; alo[mi][2] = A2.y; alo[mi][3] = A3.y;
        }
        #pragma unroll
        for (int ni = 0; ni < 4; ++ni) {
            const uint2* bp = pw2 + (n2 + 8 * ni + g) * 64 + kw + t;
            uint2 B0 = bp[0], B1 = bp[4];
            #pragma unroll
            for (int mi = 0; mi < 2; ++mi) {
                mma_bf16(acc2[mi][ni], ahi[mi][0], ahi[mi][1], ahi[mi][2], ahi[mi][3], B0.x, B1.x);
                mma_bf16(acc2[mi][ni], ahi[mi][0], ahi[mi][1], ahi[mi][2], ahi[mi][3], B0.y, B1.y);
                mma_bf16(acc2[mi][ni], alo[mi][0], alo[mi][1], alo[mi][2], alo[mi][3], B0.x, B1.x);
            }
        }
    }

    // epilogue: +b2, store ea (f32), node scatter, graph pool (shfl-reduced)
    int gmin = sGB[0];
    #pragma unroll
    for (int ni = 0; ni < 4; ++ni) {
        int cc = n2 + 8 * ni + 2 * t;
        float b2a = b2[cc], b2b = b2[cc + 1];
        float s0x = 0.f, s0y = 0.f, s1x = 0.f, s1y = 0.f;
        #pragma unroll
        for (int mi = 0; mi < 2; ++mi) {
            int el = r0 + 16 * mi + g, eh = el + 8;
            float2 lo = {acc2[mi][ni][0] + b2a, acc2[mi][ni][1] + b2b};
            float2 hi = {acc2[mi][ni][2] + b2a, acc2[mi][ni][3] + b2b};
            *(float2*)(g_ea + (size_t)(e0 + el) * 64 + cc) = lo;
            *(float2*)(g_ea + (size_t)(e0 + eh) * 64 + cc) = hi;
            red2(&g_hsum[(size_t)sCol[el] * 64 + cc], lo);
            red2(&g_hsum[(size_t)sCol[eh] * 64 + cc], hi);
            int sl = sGB[el] - gmin;
            if (sl == 0) { s0x += lo.x; s0y += lo.y; }
            else if (sl == 1) { s1x += lo.x; s1y += lo.y; }
            else red2(&geout[sGB[el] * 64 + cc], lo);
            sl = sGB[eh] - gmin;
            if (sl == 0) { s0x += hi.x; s0y += hi.y; }
            else if (sl == 1) { s1x += hi.x; s1y += hi.y; }
            else red2(&geout[sGB[eh] * 64 + cc], hi);
        }
        #pragma unroll
        for (int off = 16; off >= 4; off >>= 1) {
            s0x += __shfl_xor_sync(0xffffffffu, s0x, off);
            s0y += __shfl_xor_sync(0xffffffffu, s0y, off);
            s1x += __shfl_xor_sync(0xffffffffu, s1x, off);
            s1y += __shfl_xor_sync(0xffffffffu, s1y, off);
        }
        if (lane < 4) {
            if (s0x != 0.f) atomicAdd(&sGE[cc], s0x);
            if (s0y != 0.f) atomicAdd(&sGE[cc + 1], s0y);
            if (s1x != 0.f) atomicAdd(&sGE[64 + cc], s1x);
            if (s1y != 0.f) atomicAdd(&sGE[64 + cc + 1], s1y);
        }
    }
    __syncthreads();
    if (tid < 128) {     // flush SMEM graph pool
        int sl = tid >> 6, c = tid & 63;
        int gg = sGB[0] + sl;
        if (gg < NGR && sGE[tid] != 0.f) red1(&geout[gg * 64 + c], sGE[tid]);
    }
}

// ---------------- output head: one block per graph ----------------------------
__global__ void k_head(const float* __restrict__ Wo1, const float* __restrict__ bo1,
                       const float* __restrict__ Wo2, const float* __restrict__ bo2,
                       const float* __restrict__ Wo3, const float* __restrict__ bo3,
                       float* __restrict__ out) {
    __shared__ float aa[512];
    __shared__ float s1[128];
    __shared__ float s2[128];
    int g = blockIdx.x;
    int tid = threadIdx.x;
    float ninv = 1.f / fmaxf((float)g_cnt_ng[g], 1.f);
    float einv = 1.f / fmaxf((float)g_cnt_eg[g], 1.f);
    for (int i = tid; i < 512; i += 128) {
        float v;
        if (i < 256) {
            v = g_gnsum[(i >> 6) * NGR * 64 + g * 64 + (i & 63)] * ninv;
            out[g * 256 + i] = v;
        } else {
            int c = i - 256;
            v = g_gesum[(c >> 6) * NGR * 64 + g * 64 + (c & 63)] * einv;
            out[4096 + g * 256 + c] = v;
        }
        aa[i] = v;
    }
    __syncthreads();
    {
        float s = bo1[tid];
        for (int k = 0; k < 512; ++k) s = fmaf(aa[k], Wo1[k * 128 + tid], s);
        s1[tid] = fmaxf(s, 0.f);
    }
    __syncthreads();
    {
        float s = bo2[tid];
        for (int k = 0; k < 128; ++k) s = fmaf(s1[k], Wo2[k * 128 + tid], s);
        s2[tid] = fmaxf(s, 0.f);
    }
    __syncthreads();
    if (tid < 32) {
        float s = bo3[tid];
        for (int k = 0; k < 128; ++k) s = fmaf(s2[k], Wo3[k * 32 + tid], s);
        out[8192 + g * 32 + tid] = s;
    }
}

// ---------------- launcher ----------------------------------------------------
extern "C" void kernel_launch(void* const* d_in, const int* in_sizes, int n_in,
                              void* d_out, int out_size) {
    const float* edge_attr = (const float*)d_in[1];
    const int*   eidx      = (const int*)d_in[3];
    const int*   batch     = (const int*)d_in[4];
    const int*   eb        = (const int*)d_in[5];
    const float* W1s       = (const float*)d_in[6];
    const float* b1s       = (const float*)d_in[7];
    const float* W2s       = (const float*)d_in[8];
    const float* b2s       = (const float*)d_in[9];
    const float* Wo1       = (const float*)d_in[10];
    const float* bo1       = (const float*)d_in[11];
    const float* Wo2       = (const float*)d_in[12];
    const float* bo2       = (const float*)d_in[13];
    const float* Wo3       = (const float*)d_in[14];
    const float* bo3       = (const float*)d_in[15];
    float* out = (float*)d_out;

    cudaFuncSetAttribute((const void*)k_mlp,
                         cudaFuncAttributeMaxDynamicSharedMemorySize,
                         SMEM_MLP_BYTES);

    const int nfin_blocks = (N_CNT + 127) / 128;

    k_init<<<2048, 256>>>();
    k_wprep<<<(NLAY * 128 * 64 + NLAY * 64 * 64 + 255) / 256, 256>>>(W1s, W2s);
    k_node_cnt<<<(N_CNT + 255) / 256, 256>>>(batch);
    k_pool0<<<E_CNT / 64, 256>>>(edge_attr, eidx, eb);
    k_finhw<<<nfin_blocks, 256>>>(0, batch, b1s, 0, 1);

    for (int l = 0; l < NLAY; ++l) {
        k_mlp<<<E_CNT / TE, 256, SMEM_MLP_BYTES>>>(
            edge_attr, eidx, eb, b2s + l * 64, l);
        if (l < NLAY - 1)
            k_finhw<<<nfin_blocks, 256>>>(l + 1, batch, b1s + (l + 1) * 128, l + 1, 1);
        else
            k_finhw<<<nfin_blocks, 256>>>(NLAY, batch, b1s, 0, 0);
    }

    k_head<<<NGR, 128>>>(Wo1, bo1, Wo2, bo2, Wo3, bo3, out);
}

// round 13
// speedup vs baseline: 1.3112x; 1.0433x over previous
#include <cuda_runtime.h>
#include <cuda_bf16.h>
#include <cstdint>

// Problem constants (fixed by the dataset)
#define E_CNT   800000
#define N_CNT   50000
#define NGR     16
#define NLAY    3
#define TE      128      // edges per k_mlp block

// ---------------- scratch (device globals; no allocations allowed) ----------
__device__ float g_ea[E_CNT * 64];            // edge features (per-layer output)
__device__ float g_hw[N_CNT * 128];           // hW = h @ W1top + b1 (per layer)
__device__ float g_hcur[N_CNT * 64];          // node features h
__device__ float g_hsum[N_CNT * 64];          // scatter-sum accumulator
__device__ int   g_cnt_node[N_CNT];           // in-degree per node
__device__ int   g_cnt_ng[NGR];               // nodes per graph
__device__ int   g_cnt_eg[NGR];               // edges per graph
__device__ float g_gnsum[(NLAY + 1) * NGR * 64];  // node pools (sums)
__device__ float g_gesum[(NLAY + 1) * NGR * 64];  // edge pools (sums)
// pre-split transposed weights: packed words {hi(bf16x2), lo(bf16x2)} per 2 k
__device__ uint2 g_W1t[NLAY * 128 * 64];      // [l][n(128)][kpair(64)]
__device__ uint2 g_W2t[NLAY * 64 * 64];       // [l][n(64)][kpair(64)]

// ---------------- PTX helpers ------------------------------------------------
__device__ __forceinline__ void red4(float* p, float4 v) {
    asm volatile("red.global.add.v4.f32 [%0], {%1,%2,%3,%4};"
                 :: "l"(p), "f"(v.x), "f"(v.y), "f"(v.z), "f"(v.w) : "memory");
}
__device__ __forceinline__ void red2(float* p, float2 v) {
    asm volatile("red.global.add.v2.f32 [%0], {%1,%2};"
                 :: "l"(p), "f"(v.x), "f"(v.y) : "memory");
}
__device__ __forceinline__ void red1(float* p, float v) {
    asm volatile("red.global.add.f32 [%0], %1;" :: "l"(p), "f"(v) : "memory");
}
// split two consecutive-k f32 values into packed bf16x2 {hi word, lo word}
__device__ __forceinline__ uint2 splitpack2(float a, float b) {
    __nv_bfloat16 ha = __float2bfloat16_rn(a);
    __nv_bfloat16 hb = __float2bfloat16_rn(b);
    __nv_bfloat16 la = __float2bfloat16_rn(a - __bfloat162float(ha));
    __nv_bfloat16 lb = __float2bfloat16_rn(b - __bfloat162float(hb));
    __nv_bfloat162 hv = __halves2bfloat162(ha, hb);   // .x = even k
    __nv_bfloat162 lv = __halves2bfloat162(la, lb);
    uint2 r;
    r.x = *reinterpret_cast<uint32_t*>(&hv);
    r.y = *reinterpret_cast<uint32_t*>(&lv);
    return r;
}
// m16n8k16 bf16 mma, row.col, f32 accumulate (fragment map per PTX ISA).
// NOT volatile: pure register computation -> compiler may schedule/interleave.
__device__ __forceinline__ void mma_bf16(float* d, uint32_t a0, uint32_t a1,
                                         uint32_t a2, uint32_t a3,
                                         uint32_t b0, uint32_t b1) {
    asm("mma.sync.aligned.m16n8k16.row.col.f32.bf16.bf16.f32 "
        "{%0,%1,%2,%3}, {%4,%5,%6,%7}, {%8,%9}, {%0,%1,%2,%3};"
        : "+f"(d[0]), "+f"(d[1]), "+f"(d[2]), "+f"(d[3])
        : "r"(a0), "r"(a1), "r"(a2), "r"(a3), "r"(b0), "r"(b1));
}

// ---------------- init: zero accumulators ------------------------------------
__global__ void k_init() {
    int t = blockIdx.x * blockDim.x + threadIdx.x;
    int stride = gridDim.x * blockDim.x;
    for (int i = t; i < N_CNT * 64; i += stride) g_hsum[i] = 0.f;
    for (int i = t; i < N_CNT; i += stride) g_cnt_node[i] = 0;
    for (int i = t; i < (NLAY + 1) * NGR * 64; i += stride) {
        g_gnsum[i] = 0.f;
        g_gesum[i] = 0.f;
    }
    for (int i = t; i < NGR; i += stride) { g_cnt_ng[i] = 0; g_cnt_eg[i] = 0; }
}

// ---------------- weight prep: transpose + bf16 hi/lo split (once) -----------
__global__ void k_wprep(const float* __restrict__ W1s, const float* __restrict__ W2s) {
    int t = blockIdx.x * blockDim.x + threadIdx.x;
    if (t < NLAY * 128 * 64) {                 // W1t: l, n(128), kp(64)
        int kp = t & 63, n = (t >> 6) & 127, l = t >> 13;
        float v0 = W1s[l * 16384 + (2 * kp) * 128 + n];
        float v1 = W1s[l * 16384 + (2 * kp + 1) * 128 + n];
        g_W1t[t] = splitpack2(v0, v1);
    } else {
        int u = t - NLAY * 128 * 64;
        if (u < NLAY * 64 * 64) {              // W2t: l, n(64), kp(64)
            int kp = u & 63, n = (u >> 6) & 63, l = u >> 12;
            float v0 = W2s[l * 8192 + (2 * kp) * 64 + n];
            float v1 = W2s[l * 8192 + (2 * kp + 1) * 64 + n];
            g_W2t[u] = splitpack2(v0, v1);
        }
    }
}

// ---------------- nodes-per-graph counts --------------------------------------
__global__ void k_node_cnt(const int* __restrict__ batch) {
    int t = blockIdx.x * blockDim.x + threadIdx.x;
    if (t < N_CNT) atomicAdd(&g_cnt_ng[batch[t]], 1);
}

// ---------------- layer-0 pooling + degree counts ------------------------------
__global__ void k_pool0(const float* __restrict__ edge_attr,
                        const int* __restrict__ eidx,
                        const int* __restrict__ eb) {
    __shared__ float stg[64 * 68];
    __shared__ float sP[128];
    __shared__ int sGBl[64];
    __shared__ int sColl[64];
    __shared__ int sCnt[2];
    int tid = threadIdx.x;
    int e0 = blockIdx.x * 64;
    if (tid < 128) sP[tid] = 0.f;
    if (tid < 64) { sGBl[tid] = eb[e0 + tid]; sColl[tid] = eidx[E_CNT + e0 + tid]; }
    if (tid < 2) sCnt[tid] = 0;
    __syncthreads();
    int gmin = sGBl[0];

    #pragma unroll
    for (int i = 0; i < 4; ++i) {
        int f = tid + i * 256;                 // 1024 = 64 edges x 16 col4
        int e = f >> 4, c4 = f & 15;
        float4 v = *(const float4*)(edge_attr + (size_t)(e0 + e) * 64 + c4 * 4);
        *(float4*)&stg[e * 68 + c4 * 4] = v;
        red4(&g_hsum[(size_t)sColl[e] * 64 + c4 * 4], v);
        if (c4 == 0) {
            atomicAdd(&g_cnt_node[sColl[e]], 1);
            int sl = sGBl[e] - gmin;
            if (sl < 2) atomicAdd(&sCnt[sl], 1);
            else atomicAdd(&g_cnt_eg[sGBl[e]], 1);
        }
    }
    __syncthreads();
    {
        int q = tid >> 6, c = tid & 63;
        float s0 = 0.f, s1 = 0.f;
        #pragma unroll
        for (int r = q * 16; r < q * 16 + 16; ++r) {
            float val = stg[r * 68 + c];
            int sl = sGBl[r] - gmin;
            if (sl == 0) s0 += val;
            else if (sl == 1) s1 += val;
            else red1(&g_gesum[sGBl[r] * 64 + c], val);
        }
        if (s0 != 0.f) atomicAdd(&sP[c], s0);
        if (s1 != 0.f) atomicAdd(&sP[64 + c], s1);
    }
    __syncthreads();
    if (tid < 128) {
        int sl = tid >> 6, c = tid & 63;
        int gg = gmin + sl;
        if (gg < NGR && sP[tid] != 0.f) red1(&g_gesum[gg * 64 + c], sP[tid]);
        if (tid < 2 && gmin + tid < NGR && sCnt[tid] > 0)
            atomicAdd(&g_cnt_eg[gmin + tid], sCnt[tid]);
    }
}

// ---------------- finalize h = h_sum/max(deg,1); pool to gn; zero h_sum --------
__global__ void k_finalize(int li, const int* __restrict__ batch) {
    __shared__ float sP[128];
    __shared__ int s_gmin;
    int tid = threadIdx.x;
    int v = blockIdx.x * 16 + (tid >> 4);
    int c4 = tid & 15;
    if (tid < 128) sP[tid] = 0.f;
    if (tid == 0) s_gmin = batch[blockIdx.x * 16];
    __syncthreads();

    float4 s = *(float4*)(g_hsum + (size_t)v * 64 + c4 * 4);
    float inv = 1.f / fmaxf((float)g_cnt_node[v], 1.f);
    float4 h = {s.x * inv, s.y * inv, s.z * inv, s.w * inv};
    *(float4*)(g_hcur + (size_t)v * 64 + c4 * 4) = h;
    float4 z = {0.f, 0.f, 0.f, 0.f};
    *(float4*)(g_hsum + (size_t)v * 64 + c4 * 4) = z;

    int gb = batch[v];
    int slot = gb - s_gmin;
    if (slot < 2) {
        atomicAdd(&sP[slot * 64 + c4 * 4 + 0], h.x);
        atomicAdd(&sP[slot * 64 + c4 * 4 + 1], h.y);
        atomicAdd(&sP[slot * 64 + c4 * 4 + 2], h.z);
        atomicAdd(&sP[slot * 64 + c4 * 4 + 3], h.w);
    } else {
        red4(&g_gnsum[li * NGR * 64 + gb * 64 + c4 * 4], h);
    }
    __syncthreads();
    if (tid < 32) {
        int sl = tid >> 4, cc = (tid & 15) * 4;
        int gg = s_gmin + sl;
        if (gg < NGR) {
            float4 p = *(float4*)&sP[sl * 64 + cc];
            if (p.x != 0.f || p.y != 0.f || p.z != 0.f || p.w != 0.f)
                red4(&g_gnsum[li * NGR * 64 + gg * 64 + cc], p);
        }
    }
}

// ---------------- node GEMM: hW = h @ W1top + b1 (per layer) -------------------
#define LDH36 36
__global__ void __launch_bounds__(256) k_hw(const float* __restrict__ b1, int layer) {
    __shared__ uint2 sH[128 * LDH36];
    int tid = threadIdx.x;
    int v0 = blockIdx.x * 128;

    #pragma unroll
    for (int i = 0; i < 8; ++i) {              // 2048 float4 = 128 rows x 16
        int f = tid + i * 256;
        int r = f >> 4, c4 = f & 15;
        int node = v0 + r;
        if (node >= N_CNT) node = N_CNT - 1;
        float4 x = *(const float4*)(g_hcur + (size_t)node * 64 + c4 * 4);
        uint2 w0 = splitpack2(x.x, x.y), w1 = splitpack2(x.z, x.w);
        uint4 pk = {w0.x, w0.y, w1.x, w1.y};
        *(uint4*)&sH[r * LDH36 + c4 * 2] = pk;
    }
    __syncthreads();

    const int wid = tid >> 5, lane = tid & 31;
    const int g = lane >> 2, t = lane & 3;
    const int r0 = (wid & 3) * 32, n0 = (wid >> 2) * 64;
    const uint2* pw1 = g_W1t + layer * 128 * 64;

    float acc[2][8][4];
    #pragma unroll
    for (int mi = 0; mi < 2; ++mi)
        #pragma unroll
        for (int ni = 0; ni < 8; ++ni)
            #pragma unroll
            for (int q = 0; q < 4; ++q) acc[mi][ni][q] = 0.f;

    #pragma unroll
    for (int ks = 0; ks < 4; ++ks) {
        int kw = ks * 8;
        uint32_t ahi[2][4], alo[2][4];
        #pragma unroll
        for (int mi = 0; mi < 2; ++mi) {
            const uint2* ap = sH + (r0 + 16 * mi + g) * LDH36 + kw + t;
            uint2 A0 = ap[0], A1 = ap[8 * LDH36], A2 = ap[4], A3 = ap[8 * LDH36 + 4];
            ahi[mi][0] = A0.x; ahi[mi][1] = A1.x; ahi[mi][2] = A2.x; ahi[mi][3] = A3.x;
            alo[mi][0] = A0.y; alo[mi][1] = A1.y; alo[mi][2] = A2.y; alo[mi][3] = A3.y;
        }
        #pragma unroll
        for (int ni = 0; ni < 8; ++ni) {
            const uint2* bp = pw1 + (n0 + 8 * ni + g) * 64 + kw + t;  // kpairs 0..31
            uint2 B0 = bp[0], B1 = bp[4];
            // interleaved: alternate acc[0]/acc[1] between same-acc chains
            mma_bf16(acc[0][ni], ahi[0][0], ahi[0][1], ahi[0][2], ahi[0][3], B0.x, B1.x);
            mma_bf16(acc[1][ni], ahi[1][0], ahi[1][1], ahi[1][2], ahi[1][3], B0.x, B1.x);
            mma_bf16(acc[0][ni], ahi[0][0], ahi[0][1], ahi[0][2], ahi[0][3], B0.y, B1.y);
            mma_bf16(acc[1][ni], ahi[1][0], ahi[1][1], ahi[1][2], ahi[1][3], B0.y, B1.y);
            mma_bf16(acc[0][ni], alo[0][0], alo[0][1], alo[0][2], alo[0][3], B0.x, B1.x);
            mma_bf16(acc[1][ni], alo[1][0], alo[1][1], alo[1][2], alo[1][3], B0.x, B1.x);
        }
    }
    #pragma unroll
    for (int mi = 0; mi < 2; ++mi) {
        int vl = v0 + r0 + 16 * mi + g, vh = vl + 8;
        #pragma unroll
        for (int ni = 0; ni < 8; ++ni) {
            int cc = n0 + 8 * ni + 2 * t;
            float ba = b1[cc], bb = b1[cc + 1];
            if (vl < N_CNT) {
                float2 o = {acc[mi][ni][0] + ba, acc[mi][ni][1] + bb};
                *(float2*)(g_hw + (size_t)vl * 128 + cc) = o;
            }
            if (vh < N_CNT) {
                float2 o = {acc[mi][ni][2] + ba, acc[mi][ni][3] + bb};
                *(float2*)(g_hw + (size_t)vh * 128 + cc) = o;
            }
        }
    }
}

// ---------------- fused edge MLP (bf16x3, K-split, global W) + scatter ---------
// 128 edges / 256 threads, occ 2 (~108.5KB smem). R6 engine; interleaved mma issue.
#define LDEA 36
#define LDHD 68
#define SMEM_MLP_BYTES (128 * LDEA * 8 + 128 * LDHD * 8 + 3 * 128 * 4 + 128 * 4)

__global__ void __launch_bounds__(256, 2)
k_mlp(const float* __restrict__ edge_attr,
      const int* __restrict__ eidx, const int* __restrict__ eb,
      const float* __restrict__ b2, int layer) {
    extern __shared__ char smem[];
    uint2* sEA  = (uint2*)smem;                          // [128][36]
    uint2* sHID = (uint2*)(smem + 128 * LDEA * 8);       // [128][68]
    int* sRow = (int*)(smem + 128 * LDEA * 8 + 128 * LDHD * 8);
    int* sCol = sRow + 128;
    int* sGB  = sCol + 128;
    float* sGE = (float*)(sGB + 128);                    // [2][64]

    const float* ea_in = (layer == 0) ? edge_attr : g_ea;
    float* geout = g_gesum + (layer + 1) * NGR * 64;
    const uint2* pw1 = g_W1t + layer * 128 * 64;
    const uint2* pw2 = g_W2t + layer * 64 * 64;

    const int tid = threadIdx.x;
    const int e0 = blockIdx.x * TE;

    if (tid < 128) { sRow[tid] = eidx[e0 + tid]; sGE[tid] = 0.f; }
    else {
        int u = tid - 128;
        sCol[u] = eidx[E_CNT + e0 + u];
        sGB[u] = eb[e0 + u];
    }
    // gather ea (f32) + split -> sEA (stride 36 uint2)
    #pragma unroll
    for (int i = 0; i < 8; ++i) {
        int f = tid + i * 256;                 // 2048 float4 = 128 x 16
        int e = f >> 4, c4 = f & 15;
        float4 x = *(const float4*)(ea_in + (size_t)(e0 + e) * 64 + c4 * 4);
        uint2 w0 = splitpack2(x.x, x.y), w1 = splitpack2(x.z, x.w);
        uint4 pk = {w0.x, w0.y, w1.x, w1.y};
        *(uint4*)(sEA + e * LDEA + c4 * 2) = pk;
    }
    __syncthreads();

    const int wid = tid >> 5, lane = tid & 31;
    const int g = lane >> 2, t = lane & 3;
    const int r0 = (wid & 3) * 32;

    // ---- GEMM1-edge: acc = ea @ W1bot (K=64), tiles 32x64, B from global
    const int n0 = (wid >> 2) * 64;
    float acc[2][8][4];
    #pragma unroll
    for (int mi = 0; mi < 2; ++mi)
        #pragma unroll
        for (int ni = 0; ni < 8; ++ni)
            #pragma unroll
            for (int q = 0; q < 4; ++q) acc[mi][ni][q] = 0.f;

    #pragma unroll
    for (int ks = 0; ks < 4; ++ks) {
        int kw = ks * 8;
        uint32_t ahi[2][4], alo[2][4];
        #pragma unroll
        for (int mi = 0; mi < 2; ++mi) {
            const uint2* ap = sEA + (r0 + 16 * mi + g) * LDEA + kw + t;
            uint2 A0 = ap[0], A1 = ap[8 * LDEA], A2 = ap[4], A3 = ap[8 * LDEA + 4];
            ahi[mi][0] = A0.x; ahi[mi][1] = A1.x; ahi[mi][2] = A2.x; ahi[mi][3] = A3.x;
            alo[mi][0] = A0.y; alo[mi][1] = A1.y; alo[mi][2] = A2.y; alo[mi][3] = A3.y;
        }
        #pragma unroll
        for (int ni = 0; ni < 8; ++ni) {
            const uint2* bp = pw1 + (n0 + 8 * ni + g) * 64 + 32 + kw + t;  // kpairs 32..63
            uint2 B0 = bp[0], B1 = bp[4];
            mma_bf16(acc[0][ni], ahi[0][0], ahi[0][1], ahi[0][2], ahi[0][3], B0.x, B1.x);
            mma_bf16(acc[1][ni], ahi[1][0], ahi[1][1], ahi[1][2], ahi[1][3], B0.x, B1.x);
            mma_bf16(acc[0][ni], ahi[0][0], ahi[0][1], ahi[0][2], ahi[0][3], B0.y, B1.y);
            mma_bf16(acc[1][ni], ahi[1][0], ahi[1][1], ahi[1][2], ahi[1][3], B0.y, B1.y);
            mma_bf16(acc[0][ni], alo[0][0], alo[0][1], alo[0][2], alo[0][3], B0.x, B1.x);
            mma_bf16(acc[1][ni], alo[1][0], alo[1][1], alo[1][2], alo[1][3], B0.x, B1.x);
        }
    }

    // mid epilogue: hid = relu(acc + hW[row]); split -> sHID
    #pragma unroll
    for (int mi = 0; mi < 2; ++mi) {
        int el = r0 + 16 * mi + g, eh = el + 8;
        const float* hwl = g_hw + (size_t)sRow[el] * 128;
        const float* hwh = g_hw + (size_t)sRow[eh] * 128;
        #pragma unroll
        for (int ni = 0; ni < 8; ++ni) {
            int cc = n0 + 8 * ni + 2 * t;
            float2 hl = *(const float2*)(hwl + cc);
            float2 hh = *(const float2*)(hwh + cc);
            float v0 = fmaxf(acc[mi][ni][0] + hl.x, 0.f);
            float v1 = fmaxf(acc[mi][ni][1] + hl.y, 0.f);
            float v2 = fmaxf(acc[mi][ni][2] + hh.x, 0.f);
            float v3 = fmaxf(acc[mi][ni][3] + hh.y, 0.f);
            int wd = (n0 >> 1) + 4 * ni + t;
            sHID[el * LDHD + wd] = splitpack2(v0, v1);
            sHID[eh * LDHD + wd] = splitpack2(v2, v3);
        }
    }
    __syncthreads();

    // ---- GEMM2: out = hid @ W2 (K=128), tiles 32x32, B from global
    const int n2 = (wid >> 2) * 32;
    float acc2[2][4][4];
    #pragma unroll
    for (int mi = 0; mi < 2; ++mi)
        #pragma unroll
        for (int ni = 0; ni < 4; ++ni)
            #pragma unroll
            for (int q = 0; q < 4; ++q) acc2[mi][ni][q] = 0.f;

    #pragma unroll
    for (int ks = 0; ks < 8; ++ks) {
        int kw = ks * 8;
        uint32_t ahi[2][4], alo[2][4];
        #pragma unroll
        for (int mi = 0; mi < 2; ++mi) {
            const uint2* ap = sHID + (r0 + 16 * mi + g) * LDHD + kw + t;
            uint2 A0 = ap[0], A1 = ap[8 * LDHD], A2 = ap[4], A3 = ap[8 * LDHD + 4];
            ahi[mi][0] = A0.x; ahi[mi][1] = A1.x; ahi[mi][2] = A2.x; ahi[mi][3] = A3.x;
            alo[mi][0] = A0.y; alo[mi][1] = A1.y; alo[mi][2] = A2.y; alo[mi][3] = A3.y;
        }
        #pragma unroll
        for (int ni = 0; ni < 4; ++ni) {
            const uint2* bp = pw2 + (n2 + 8 * ni + g) * 64 + kw + t;
            uint2 B0 = bp[0], B1 = bp[4];
            mma_bf16(acc2[0][ni], ahi[0][0], ahi[0][1], ahi[0][2], ahi[0][3], B0.x, B1.x);
            mma_bf16(acc2[1][ni], ahi[1][0], ahi[1][1], ahi[1][2], ahi[1][3], B0.x, B1.x);
            mma_bf16(acc2[0][ni], ahi[0][0], ahi[0][1], ahi[0][2], ahi[0][3], B0.y, B1.y);
            mma_bf16(acc2[1][ni], ahi[1][0], ahi[1][1], ahi[1][2], ahi[1][3], B0.y, B1.y);
            mma_bf16(acc2[0][ni], alo[0][0], alo[0][1], alo[0][2], alo[0][3], B0.x, B1.x);
            mma_bf16(acc2[1][ni], alo[1][0], alo[1][1], alo[1][2], alo[1][3], B0.x, B1.x);
        }
    }

    // epilogue: +b2, store ea (f32), node scatter, graph pool (shfl-reduced)
    int gmin = sGB[0];
    #pragma unroll
    for (int ni = 0; ni < 4; ++ni) {
        int cc = n2 + 8 * ni + 2 * t;
        float b2a = b2[cc], b2b = b2[cc + 1];
        float s0x = 0.f, s0y = 0.f, s1x = 0.f, s1y = 0.f;
        #pragma unroll
        for (int mi = 0; mi < 2; ++mi) {
            int el = r0 + 16 * mi + g, eh = el + 8;
            float2 lo = {acc2[mi][ni][0] + b2a, acc2[mi][ni][1] + b2b};
            float2 hi = {acc2[mi][ni][2] + b2a, acc2[mi][ni][3] + b2b};
            *(float2*)(g_ea + (size_t)(e0 + el) * 64 + cc) = lo;
            *(float2*)(g_ea + (size_t)(e0 + eh) * 64 + cc) = hi;
            red2(&g_hsum[(size_t)sCol[el] * 64 + cc], lo);
            red2(&g_hsum[(size_t)sCol[eh] * 64 + cc], hi);
            int sl = sGB[el] - gmin;
            if (sl == 0) { s0x += lo.x; s0y += lo.y; }
            else if (sl == 1) { s1x += lo.x; s1y += lo.y; }
            else red2(&geout[sGB[el] * 64 + cc], lo);
            sl = sGB[eh] - gmin;
            if (sl == 0) { s0x += hi.x; s0y += hi.y; }
            else if (sl == 1) { s1x += hi.x; s1y += hi.y; }
            else red2(&geout[sGB[eh] * 64 + cc], hi);
        }
        #pragma unroll
        for (int off = 16; off >= 4; off >>= 1) {
            s0x += __shfl_xor_sync(0xffffffffu, s0x, off);
            s0y += __shfl_xor_sync(0xffffffffu, s0y, off);
            s1x += __shfl_xor_sync(0xffffffffu, s1x, off);
            s1y += __shfl_xor_sync(0xffffffffu, s1y, off);
        }
        if (lane < 4) {
            if (s0x != 0.f) atomicAdd(&sGE[cc], s0x);
            if (s0y != 0.f) atomicAdd(&sGE[cc + 1], s0y);
            if (s1x != 0.f) atomicAdd(&sGE[64 + cc], s1x);
            if (s1y != 0.f) atomicAdd(&sGE[64 + cc + 1], s1y);
        }
    }
    __syncthreads();
    if (tid < 128) {     // flush SMEM graph pool
        int sl = tid >> 6, c = tid & 63;
        int gg = sGB[0] + sl;
        if (gg < NGR && sGE[tid] != 0.f) red1(&geout[gg * 64 + c], sGE[tid]);
    }
}

// ---------------- output head: one block per graph ----------------------------
__global__ void k_head(const float* __restrict__ Wo1, const float* __restrict__ bo1,
                       const float* __restrict__ Wo2, const float* __restrict__ bo2,
                       const float* __restrict__ Wo3, const float* __restrict__ bo3,
                       float* __restrict__ out) {
    __shared__ float aa[512];
    __shared__ float s1[128];
    __shared__ float s2[128];
    int g = blockIdx.x;
    int tid = threadIdx.x;
    float ninv = 1.f / fmaxf((float)g_cnt_ng[g], 1.f);
    float einv = 1.f / fmaxf((float)g_cnt_eg[g], 1.f);
    for (int i = tid; i < 512; i += 128) {
        float v;
        if (i < 256) {
            v = g_gnsum[(i >> 6) * NGR * 64 + g * 64 + (i & 63)] * ninv;
            out[g * 256 + i] = v;
        } else {
            int c = i - 256;
            v = g_gesum[(c >> 6) * NGR * 64 + g * 64 + (c & 63)] * einv;
            out[4096 + g * 256 + c] = v;
        }
        aa[i] = v;
    }
    __syncthreads();
    {
        float s = bo1[tid];
        for (int k = 0; k < 512; ++k) s = fmaf(aa[k], Wo1[k * 128 + tid], s);
        s1[tid] = fmaxf(s, 0.f);
    }
    __syncthreads();
    {
        float s = bo2[tid];
        for (int k = 0; k < 128; ++k) s = fmaf(s1[k], Wo2[k * 128 + tid], s);
        s2[tid] = fmaxf(s, 0.f);
    }
    __syncthreads();
    if (tid < 32) {
        float s = bo3[tid];
        for (int k = 0; k < 128; ++k) s = fmaf(s2[k], Wo3[k * 32 + tid], s);
        out[8192 + g * 32 + tid] = s;
    }
}

// ---------------- launcher ----------------------------------------------------
extern "C" void kernel_launch(void* const* d_in, const int* in_sizes, int n_in,
                              void* d_out, int out_size) {
    const float* edge_attr = (const float*)d_in[1];
    const int*   eidx      = (const int*)d_in[3];
    const int*   batch     = (const int*)d_in[4];
    const int*   eb        = (const int*)d_in[5];
    const float* W1s       = (const float*)d_in[6];
    const float* b1s       = (const float*)d_in[7];
    const float* W2s       = (const float*)d_in[8];
    const float* b2s       = (const float*)d_in[9];
    const float* Wo1       = (const float*)d_in[10];
    const float* bo1       = (const float*)d_in[11];
    const float* Wo2       = (const float*)d_in[12];
    const float* bo2       = (const float*)d_in[13];
    const float* Wo3       = (const float*)d_in[14];
    const float* bo3       = (const float*)d_in[15];
    float* out = (float*)d_out;

    cudaFuncSetAttribute((const void*)k_mlp,
                         cudaFuncAttributeMaxDynamicSharedMemorySize,
                         SMEM_MLP_BYTES);

    k_init<<<2048, 256>>>();
    k_wprep<<<(NLAY * 128 * 64 + NLAY * 64 * 64 + 255) / 256, 256>>>(W1s, W2s);
    k_node_cnt<<<(N_CNT + 255) / 256, 256>>>(batch);
    k_pool0<<<E_CNT / 64, 256>>>(edge_attr, eidx, eb);
    k_finalize<<<N_CNT / 16, 256>>>(0, batch);

    for (int l = 0; l < NLAY; ++l) {
        k_hw<<<(N_CNT + 127) / 128, 256>>>(b1s + l * 128, l);
        k_mlp<<<E_CNT / TE, 256, SMEM_MLP_BYTES>>>(
            edge_attr, eidx, eb, b2s + l * 64, l);
        k_finalize<<<N_CNT / 16, 256>>>(l + 1, batch);
    }

    k_head<<<NGR, 128>>>(Wo1, bo1, Wo2, bo2, Wo3, bo3, out);
}

// round 14
// speedup vs baseline: 1.3254x; 1.0108x over previous
#include <cuda_runtime.h>
#include <cuda_bf16.h>
#include <cstdint>

// Problem constants (fixed by the dataset)
#define E_CNT   800000
#define N_CNT   50000
#define NGR     16
#define NLAY    3
#define TE      64       // edges per k_mlp block (128 threads, 4 warps)

// ---------------- scratch (device globals; no allocations allowed) ----------
__device__ float g_ea[E_CNT * 64];            // edge features (per-layer output)
__device__ float g_hw[N_CNT * 128];           // hW = h @ W1top + b1 (per layer)
__device__ float g_hcur[N_CNT * 64];          // node features h
__device__ float g_hsum[N_CNT * 64];          // scatter-sum accumulator
__device__ int   g_cnt_node[N_CNT];           // in-degree per node
__device__ int   g_cnt_ng[NGR];               // nodes per graph
__device__ int   g_cnt_eg[NGR];               // edges per graph
__device__ float g_gnsum[(NLAY + 1) * NGR * 64];  // node pools (sums)
__device__ float g_gesum[(NLAY + 1) * NGR * 64];  // edge pools (sums)
// pre-split transposed weights: packed words {hi(bf16x2), lo(bf16x2)} per 2 k
__device__ uint2 g_W1t[NLAY * 128 * 64];      // [l][n(128)][kpair(64)]
__device__ uint2 g_W2t[NLAY * 64 * 64];       // [l][n(64)][kpair(64)]

// ---------------- PTX helpers ------------------------------------------------
__device__ __forceinline__ void red4(float* p, float4 v) {
    asm volatile("red.global.add.v4.f32 [%0], {%1,%2,%3,%4};"
                 :: "l"(p), "f"(v.x), "f"(v.y), "f"(v.z), "f"(v.w) : "memory");
}
__device__ __forceinline__ void red2(float* p, float2 v) {
    asm volatile("red.global.add.v2.f32 [%0], {%1,%2};"
                 :: "l"(p), "f"(v.x), "f"(v.y) : "memory");
}
__device__ __forceinline__ void red1(float* p, float v) {
    asm volatile("red.global.add.f32 [%0], %1;" :: "l"(p), "f"(v) : "memory");
}
// split two consecutive-k f32 values into packed bf16x2 {hi word, lo word}
__device__ __forceinline__ uint2 splitpack2(float a, float b) {
    __nv_bfloat16 ha = __float2bfloat16_rn(a);
    __nv_bfloat16 hb = __float2bfloat16_rn(b);
    __nv_bfloat16 la = __float2bfloat16_rn(a - __bfloat162float(ha));
    __nv_bfloat16 lb = __float2bfloat16_rn(b - __bfloat162float(hb));
    __nv_bfloat162 hv = __halves2bfloat162(ha, hb);   // .x = even k
    __nv_bfloat162 lv = __halves2bfloat162(la, lb);
    uint2 r;
    r.x = *reinterpret_cast<uint32_t*>(&hv);
    r.y = *reinterpret_cast<uint32_t*>(&lv);
    return r;
}
// m16n8k16 bf16 mma, row.col, f32 accumulate (fragment map per PTX ISA).
__device__ __forceinline__ void mma_bf16(float* d, uint32_t a0, uint32_t a1,
                                         uint32_t a2, uint32_t a3,
                                         uint32_t b0, uint32_t b1) {
    asm("mma.sync.aligned.m16n8k16.row.col.f32.bf16.bf16.f32 "
        "{%0,%1,%2,%3}, {%4,%5,%6,%7}, {%8,%9}, {%0,%1,%2,%3};"
        : "+f"(d[0]), "+f"(d[1]), "+f"(d[2]), "+f"(d[3])
        : "r"(a0), "r"(a1), "r"(a2), "r"(a3), "r"(b0), "r"(b1));
}

// ---------------- init: zero accumulators ------------------------------------
__global__ void k_init() {
    int t = blockIdx.x * blockDim.x + threadIdx.x;
    int stride = gridDim.x * blockDim.x;
    for (int i = t; i < N_CNT * 64; i += stride) g_hsum[i] = 0.f;
    for (int i = t; i < N_CNT; i += stride) g_cnt_node[i] = 0;
    for (int i = t; i < (NLAY + 1) * NGR * 64; i += stride) {
        g_gnsum[i] = 0.f;
        g_gesum[i] = 0.f;
    }
    for (int i = t; i < NGR; i += stride) { g_cnt_ng[i] = 0; g_cnt_eg[i] = 0; }
}

// ---------------- weight prep: transpose + bf16 hi/lo split (once) -----------
__global__ void k_wprep(const float* __restrict__ W1s, const float* __restrict__ W2s) {
    int t = blockIdx.x * blockDim.x + threadIdx.x;
    if (t < NLAY * 128 * 64) {                 // W1t: l, n(128), kp(64)
        int kp = t & 63, n = (t >> 6) & 127, l = t >> 13;
        float v0 = W1s[l * 16384 + (2 * kp) * 128 + n];
        float v1 = W1s[l * 16384 + (2 * kp + 1) * 128 + n];
        g_W1t[t] = splitpack2(v0, v1);
    } else {
        int u = t - NLAY * 128 * 64;
        if (u < NLAY * 64 * 64) {              // W2t: l, n(64), kp(64)
            int kp = u & 63, n = (u >> 6) & 63, l = u >> 12;
            float v0 = W2s[l * 8192 + (2 * kp) * 64 + n];
            float v1 = W2s[l * 8192 + (2 * kp + 1) * 64 + n];
            g_W2t[u] = splitpack2(v0, v1);
        }
    }
}

// ---------------- nodes-per-graph counts --------------------------------------
__global__ void k_node_cnt(const int* __restrict__ batch) {
    int t = blockIdx.x * blockDim.x + threadIdx.x;
    if (t < N_CNT) atomicAdd(&g_cnt_ng[batch[t]], 1);
}

// ---------------- layer-0 pooling + degree counts ------------------------------
__global__ void k_pool0(const float* __restrict__ edge_attr,
                        const int* __restrict__ eidx,
                        const int* __restrict__ eb) {
    __shared__ float stg[64 * 68];
    __shared__ float sP[128];
    __shared__ int sGBl[64];
    __shared__ int sColl[64];
    __shared__ int sCnt[2];
    int tid = threadIdx.x;
    int e0 = blockIdx.x * 64;
    if (tid < 128) sP[tid] = 0.f;
    if (tid < 64) { sGBl[tid] = eb[e0 + tid]; sColl[tid] = eidx[E_CNT + e0 + tid]; }
    if (tid < 2) sCnt[tid] = 0;
    __syncthreads();
    int gmin = sGBl[0];

    #pragma unroll
    for (int i = 0; i < 4; ++i) {
        int f = tid + i * 256;                 // 1024 = 64 edges x 16 col4
        int e = f >> 4, c4 = f & 15;
        float4 v = *(const float4*)(edge_attr + (size_t)(e0 + e) * 64 + c4 * 4);
        *(float4*)&stg[e * 68 + c4 * 4] = v;
        red4(&g_hsum[(size_t)sColl[e] * 64 + c4 * 4], v);
        if (c4 == 0) {
            atomicAdd(&g_cnt_node[sColl[e]], 1);
            int sl = sGBl[e] - gmin;
            if (sl < 2) atomicAdd(&sCnt[sl], 1);
            else atomicAdd(&g_cnt_eg[sGBl[e]], 1);
        }
    }
    __syncthreads();
    {
        int q = tid >> 6, c = tid & 63;
        float s0 = 0.f, s1 = 0.f;
        #pragma unroll
        for (int r = q * 16; r < q * 16 + 16; ++r) {
            float val = stg[r * 68 + c];
            int sl = sGBl[r] - gmin;
            if (sl == 0) s0 += val;
            else if (sl == 1) s1 += val;
            else red1(&g_gesum[sGBl[r] * 64 + c], val);
        }
        if (s0 != 0.f) atomicAdd(&sP[c], s0);
        if (s1 != 0.f) atomicAdd(&sP[64 + c], s1);
    }
    __syncthreads();
    if (tid < 128) {
        int sl = tid >> 6, c = tid & 63;
        int gg = gmin + sl;
        if (gg < NGR && sP[tid] != 0.f) red1(&g_gesum[gg * 64 + c], sP[tid]);
        if (tid < 2 && gmin + tid < NGR && sCnt[tid] > 0)
            atomicAdd(&g_cnt_eg[gmin + tid], sCnt[tid]);
    }
}

// ---------------- finalize h = h_sum/max(deg,1); pool to gn; zero h_sum --------
__global__ void k_finalize(int li, const int* __restrict__ batch) {
    __shared__ float sP[128];
    __shared__ int s_gmin;
    int tid = threadIdx.x;
    int v = blockIdx.x * 16 + (tid >> 4);
    int c4 = tid & 15;
    if (tid < 128) sP[tid] = 0.f;
    if (tid == 0) s_gmin = batch[blockIdx.x * 16];
    __syncthreads();

    float4 s = *(float4*)(g_hsum + (size_t)v * 64 + c4 * 4);
    float inv = 1.f / fmaxf((float)g_cnt_node[v], 1.f);
    float4 h = {s.x * inv, s.y * inv, s.z * inv, s.w * inv};
    *(float4*)(g_hcur + (size_t)v * 64 + c4 * 4) = h;
    float4 z = {0.f, 0.f, 0.f, 0.f};
    *(float4*)(g_hsum + (size_t)v * 64 + c4 * 4) = z;

    int gb = batch[v];
    int slot = gb - s_gmin;
    if (slot < 2) {
        atomicAdd(&sP[slot * 64 + c4 * 4 + 0], h.x);
        atomicAdd(&sP[slot * 64 + c4 * 4 + 1], h.y);
        atomicAdd(&sP[slot * 64 + c4 * 4 + 2], h.z);
        atomicAdd(&sP[slot * 64 + c4 * 4 + 3], h.w);
    } else {
        red4(&g_gnsum[li * NGR * 64 + gb * 64 + c4 * 4], h);
    }
    __syncthreads();
    if (tid < 32) {
        int sl = tid >> 4, cc = (tid & 15) * 4;
        int gg = s_gmin + sl;
        if (gg < NGR) {
            float4 p = *(float4*)&sP[sl * 64 + cc];
            if (p.x != 0.f || p.y != 0.f || p.z != 0.f || p.w != 0.f)
                red4(&g_gnsum[li * NGR * 64 + gg * 64 + cc], p);
        }
    }
}

// ---------------- node GEMM: hW = h @ W1top + b1 (per layer) -------------------
#define LDH36 36
__global__ void __launch_bounds__(256) k_hw(const float* __restrict__ b1, int layer) {
    __shared__ uint2 sH[128 * LDH36];
    int tid = threadIdx.x;
    int v0 = blockIdx.x * 128;

    #pragma unroll
    for (int i = 0; i < 8; ++i) {              // 2048 float4 = 128 rows x 16
        int f = tid + i * 256;
        int r = f >> 4, c4 = f & 15;
        int node = v0 + r;
        if (node >= N_CNT) node = N_CNT - 1;
        float4 x = *(const float4*)(g_hcur + (size_t)node * 64 + c4 * 4);
        uint2 w0 = splitpack2(x.x, x.y), w1 = splitpack2(x.z, x.w);
        uint4 pk = {w0.x, w0.y, w1.x, w1.y};
        *(uint4*)&sH[r * LDH36 + c4 * 2] = pk;
    }
    __syncthreads();

    const int wid = tid >> 5, lane = tid & 31;
    const int g = lane >> 2, t = lane & 3;
    const int r0 = (wid & 3) * 32, n0 = (wid >> 2) * 64;
    const uint2* pw1 = g_W1t + layer * 128 * 64;

    float acc[2][8][4];
    #pragma unroll
    for (int mi = 0; mi < 2; ++mi)
        #pragma unroll
        for (int ni = 0; ni < 8; ++ni)
            #pragma unroll
            for (int q = 0; q < 4; ++q) acc[mi][ni][q] = 0.f;

    #pragma unroll
    for (int ks = 0; ks < 4; ++ks) {
        int kw = ks * 8;
        uint32_t ahi[2][4], alo[2][4];
        #pragma unroll
        for (int mi = 0; mi < 2; ++mi) {
            const uint2* ap = sH + (r0 + 16 * mi + g) * LDH36 + kw + t;
            uint2 A0 = ap[0], A1 = ap[8 * LDH36], A2 = ap[4], A3 = ap[8 * LDH36 + 4];
            ahi[mi][0] = A0.x; ahi[mi][1] = A1.x; ahi[mi][2] = A2.x; ahi[mi][3] = A3.x;
            alo[mi][0] = A0.y; alo[mi][1] = A1.y; alo[mi][2] = A2.y; alo[mi][3] = A3.y;
        }
        #pragma unroll
        for (int ni = 0; ni < 8; ++ni) {
            const uint2* bp = pw1 + (n0 + 8 * ni + g) * 64 + kw + t;  // kpairs 0..31
            uint2 B0 = bp[0], B1 = bp[4];
            mma_bf16(acc[0][ni], ahi[0][0], ahi[0][1], ahi[0][2], ahi[0][3], B0.x, B1.x);
            mma_bf16(acc[1][ni], ahi[1][0], ahi[1][1], ahi[1][2], ahi[1][3], B0.x, B1.x);
            mma_bf16(acc[0][ni], ahi[0][0], ahi[0][1], ahi[0][2], ahi[0][3], B0.y, B1.y);
            mma_bf16(acc[1][ni], ahi[1][0], ahi[1][1], ahi[1][2], ahi[1][3], B0.y, B1.y);
            mma_bf16(acc[0][ni], alo[0][0], alo[0][1], alo[0][2], alo[0][3], B0.x, B1.x);
            mma_bf16(acc[1][ni], alo[1][0], alo[1][1], alo[1][2], alo[1][3], B0.x, B1.x);
        }
    }
    #pragma unroll
    for (int mi = 0; mi < 2; ++mi) {
        int vl = v0 + r0 + 16 * mi + g, vh = vl + 8;
        #pragma unroll
        for (int ni = 0; ni < 8; ++ni) {
            int cc = n0 + 8 * ni + 2 * t;
            float ba = b1[cc], bb = b1[cc + 1];
            if (vl < N_CNT) {
                float2 o = {acc[mi][ni][0] + ba, acc[mi][ni][1] + bb};
                *(float2*)(g_hw + (size_t)vl * 128 + cc) = o;
            }
            if (vh < N_CNT) {
                float2 o = {acc[mi][ni][2] + ba, acc[mi][ni][3] + bb};
                *(float2*)(g_hw + (size_t)vh * 128 + cc) = o;
            }
        }
    }
}

// ---------------- fused edge MLP (bf16x3, K-split, global W) + scatter ---------
// 64 edges / 128 threads (4 warps), occ 4 (~54.5KB smem): 4 phase domains per
// SM hide each other's gather/epilogue phases. Warp tiles identical to R6.
#define LDEA 36
#define LDHD 68
#define SMEM_MLP_BYTES (64 * LDEA * 8 + 64 * LDHD * 8 + 3 * 64 * 4 + 128 * 4)

__global__ void __launch_bounds__(128, 4)
k_mlp(const float* __restrict__ edge_attr,
      const int* __restrict__ eidx, const int* __restrict__ eb,
      const float* __restrict__ b2, int layer) {
    extern __shared__ char smem[];
    uint2* sEA  = (uint2*)smem;                          // [64][36]
    uint2* sHID = (uint2*)(smem + 64 * LDEA * 8);        // [64][68]
    int* sRow = (int*)(smem + 64 * LDEA * 8 + 64 * LDHD * 8);
    int* sCol = sRow + 64;
    int* sGB  = sCol + 64;
    float* sGE = (float*)(sGB + 64);                     // [2][64]

    const float* ea_in = (layer == 0) ? edge_attr : g_ea;
    float* geout = g_gesum + (layer + 1) * NGR * 64;
    const uint2* pw1 = g_W1t + layer * 128 * 64;
    const uint2* pw2 = g_W2t + layer * 64 * 64;

    const int tid = threadIdx.x;
    const int e0 = blockIdx.x * TE;

    if (tid < 64) sRow[tid] = eidx[e0 + tid];
    else { sCol[tid - 64] = eidx[E_CNT + e0 + tid - 64]; sGB[tid - 64] = eb[e0 + tid - 64]; }
    sGE[tid] = 0.f;

    // gather ea (f32) + split -> sEA (stride 36 uint2)
    #pragma unroll
    for (int i = 0; i < 8; ++i) {
        int f = tid + i * 128;                 // 1024 float4 = 64 x 16
        int e = f >> 4, c4 = f & 15;
        float4 x = *(const float4*)(ea_in + (size_t)(e0 + e) * 64 + c4 * 4);
        uint2 w0 = splitpack2(x.x, x.y), w1 = splitpack2(x.z, x.w);
        uint4 pk = {w0.x, w0.y, w1.x, w1.y};
        *(uint4*)(sEA + e * LDEA + c4 * 2) = pk;
    }
    __syncthreads();

    const int wid = tid >> 5, lane = tid & 31;
    const int g = lane >> 2, t = lane & 3;
    const int r0 = (wid & 1) * 32;             // row group
    const int n0 = (wid >> 1) * 64;            // n group (GEMM1)

    // ---- GEMM1-edge: acc = ea @ W1bot (K=64), tiles 32x64, B from global
    float acc[2][8][4];
    #pragma unroll
    for (int mi = 0; mi < 2; ++mi)
        #pragma unroll
        for (int ni = 0; ni < 8; ++ni)
            #pragma unroll
            for (int q = 0; q < 4; ++q) acc[mi][ni][q] = 0.f;

    #pragma unroll
    for (int ks = 0; ks < 4; ++ks) {
        int kw = ks * 8;
        uint32_t ahi[2][4], alo[2][4];
        #pragma unroll
        for (int mi = 0; mi < 2; ++mi) {
            const uint2* ap = sEA + (r0 + 16 * mi + g) * LDEA + kw + t;
            uint2 A0 = ap[0], A1 = ap[8 * LDEA], A2 = ap[4], A3 = ap[8 * LDEA + 4];
            ahi[mi][0] = A0.x; ahi[mi][1] = A1.x; ahi[mi][2] = A2.x; ahi[mi][3] = A3.x;
            alo[mi][0] = A0.y; alo[mi][1] = A1.y; alo[mi][2] = A2.y; alo[mi][3] = A3.y;
        }
        #pragma unroll
        for (int ni = 0; ni < 8; ++ni) {
            const uint2* bp = pw1 + (n0 + 8 * ni + g) * 64 + 32 + kw + t;  // kpairs 32..63
            uint2 B0 = bp[0], B1 = bp[4];
            mma_bf16(acc[0][ni], ahi[0][0], ahi[0][1], ahi[0][2], ahi[0][3], B0.x, B1.x);
            mma_bf16(acc[1][ni], ahi[1][0], ahi[1][1], ahi[1][2], ahi[1][3], B0.x, B1.x);
            mma_bf16(acc[0][ni], ahi[0][0], ahi[0][1], ahi[0][2], ahi[0][3], B0.y, B1.y);
            mma_bf16(acc[1][ni], ahi[1][0], ahi[1][1], ahi[1][2], ahi[1][3], B0.y, B1.y);
            mma_bf16(acc[0][ni], alo[0][0], alo[0][1], alo[0][2], alo[0][3], B0.x, B1.x);
            mma_bf16(acc[1][ni], alo[1][0], alo[1][1], alo[1][2], alo[1][3], B0.x, B1.x);
        }
    }

    // mid epilogue: hid = relu(acc + hW[row]); split -> sHID
    #pragma unroll
    for (int mi = 0; mi < 2; ++mi) {
        int el = r0 + 16 * mi + g, eh = el + 8;
        const float* hwl = g_hw + (size_t)sRow[el] * 128;
        const float* hwh = g_hw + (size_t)sRow[eh] * 128;
        #pragma unroll
        for (int ni = 0; ni < 8; ++ni) {
            int cc = n0 + 8 * ni + 2 * t;
            float2 hl = *(const float2*)(hwl + cc);
            float2 hh = *(const float2*)(hwh + cc);
            float v0 = fmaxf(acc[mi][ni][0] + hl.x, 0.f);
            float v1 = fmaxf(acc[mi][ni][1] + hl.y, 0.f);
            float v2 = fmaxf(acc[mi][ni][2] + hh.x, 0.f);
            float v3 = fmaxf(acc[mi][ni][3] + hh.y, 0.f);
            int wd = (n0 >> 1) + 4 * ni + t;
            sHID[el * LDHD + wd] = splitpack2(v0, v1);
            sHID[eh * LDHD + wd] = splitpack2(v2, v3);
        }
    }
    __syncthreads();

    // ---- GEMM2: out = hid @ W2 (K=128), tiles 32x32, B from global
    const int n2 = (wid >> 1) * 32;
    float acc2[2][4][4];
    #pragma unroll
    for (int mi = 0; mi < 2; ++mi)
        #pragma unroll
        for (int ni = 0; ni < 4; ++ni)
            #pragma unroll
            for (int q = 0; q < 4; ++q) acc2[mi][ni][q] = 0.f;

    #pragma unroll
    for (int ks = 0; ks < 8; ++ks) {
        int kw = ks * 8;
        uint32_t ahi[2][4], alo[2][4];
        #pragma unroll
        for (int mi = 0; mi < 2; ++mi) {
            const uint2* ap = sHID + (r0 + 16 * mi + g) * LDHD + kw + t;
            uint2 A0 = ap[0], A1 = ap[8 * LDHD], A2 = ap[4], A3 = ap[8 * LDHD + 4];
            ahi[mi][0] = A0.x; ahi[mi][1] = A1.x; ahi[mi][2] = A2.x; ahi[mi][3] = A3.x;
            alo[mi][0] = A0.y; alo[mi][1] = A1.y; alo[mi][2] = A2.y; alo[mi][3] = A3.y;
        }
        #pragma unroll
        for (int ni = 0; ni < 4; ++ni) {
            const uint2* bp = pw2 + (n2 + 8 * ni + g) * 64 + kw + t;
            uint2 B0 = bp[0], B1 = bp[4];
            mma_bf16(acc2[0][ni], ahi[0][0], ahi[0][1], ahi[0][2], ahi[0][3], B0.x, B1.x);
            mma_bf16(acc2[1][ni], ahi[1][0], ahi[1][1], ahi[1][2], ahi[1][3], B0.x, B1.x);
            mma_bf16(acc2[0][ni], ahi[0][0], ahi[0][1], ahi[0][2], ahi[0][3], B0.y, B1.y);
            mma_bf16(acc2[1][ni], ahi[1][0], ahi[1][1], ahi[1][2], ahi[1][3], B0.y, B1.y);
            mma_bf16(acc2[0][ni], alo[0][0], alo[0][1], alo[0][2], alo[0][3], B0.x, B1.x);
            mma_bf16(acc2[1][ni], alo[1][0], alo[1][1], alo[1][2], alo[1][3], B0.x, B1.x);
        }
    }

    // epilogue: +b2, store ea (f32), node scatter, graph pool (shfl-reduced)
    int gmin = sGB[0];
    #pragma unroll
    for (int ni = 0; ni < 4; ++ni) {
        int cc = n2 + 8 * ni + 2 * t;
        float b2a = b2[cc], b2b = b2[cc + 1];
        float s0x = 0.f, s0y = 0.f, s1x = 0.f, s1y = 0.f;
        #pragma unroll
        for (int mi = 0; mi < 2; ++mi) {
            int el = r0 + 16 * mi + g, eh = el + 8;
            float2 lo = {acc2[mi][ni][0] + b2a, acc2[mi][ni][1] + b2b};
            float2 hi = {acc2[mi][ni][2] + b2a, acc2[mi][ni][3] + b2b};
            *(float2*)(g_ea + (size_t)(e0 + el) * 64 + cc) = lo;
            *(float2*)(g_ea + (size_t)(e0 + eh) * 64 + cc) = hi;
            red2(&g_hsum[(size_t)sCol[el] * 64 + cc], lo);
            red2(&g_hsum[(size_t)sCol[eh] * 64 + cc], hi);
            int sl = sGB[el] - gmin;
            if (sl == 0) { s0x += lo.x; s0y += lo.y; }
            else if (sl == 1) { s1x += lo.x; s1y += lo.y; }
            else red2(&geout[sGB[el] * 64 + cc], lo);
            sl = sGB[eh] - gmin;
            if (sl == 0) { s0x += hi.x; s0y += hi.y; }
            else if (sl == 1) { s1x += hi.x; s1y += hi.y; }
            else red2(&geout[sGB[eh] * 64 + cc], hi);
        }
        #pragma unroll
        for (int off = 16; off >= 4; off >>= 1) {
            s0x += __shfl_xor_sync(0xffffffffu, s0x, off);
            s0y += __shfl_xor_sync(0xffffffffu, s0y, off);
            s1x += __shfl_xor_sync(0xffffffffu, s1x, off);
            s1y += __shfl_xor_sync(0xffffffffu, s1y, off);
        }
        if (lane < 4) {
            if (s0x != 0.f) atomicAdd(&sGE[cc], s0x);
            if (s0y != 0.f) atomicAdd(&sGE[cc + 1], s0y);
            if (s1x != 0.f) atomicAdd(&sGE[64 + cc], s1x);
            if (s1y != 0.f) atomicAdd(&sGE[64 + cc + 1], s1y);
        }
    }
    __syncthreads();
    {   // flush SMEM graph pool (128 threads cover [2][64])
        int sl = tid >> 6, c = tid & 63;
        int gg = sGB[0] + sl;
        if (gg < NGR && sGE[tid] != 0.f) red1(&geout[gg * 64 + c], sGE[tid]);
    }
}

// ---------------- output head: one block per graph ----------------------------
__global__ void k_head(const float* __restrict__ Wo1, const float* __restrict__ bo1,
                       const float* __restrict__ Wo2, const float* __restrict__ bo2,
                       const float* __restrict__ Wo3, const float* __restrict__ bo3,
                       float* __restrict__ out) {
    __shared__ float aa[512];
    __shared__ float s1[128];
    __shared__ float s2[128];
    int g = blockIdx.x;
    int tid = threadIdx.x;
    float ninv = 1.f / fmaxf((float)g_cnt_ng[g], 1.f);
    float einv = 1.f / fmaxf((float)g_cnt_eg[g], 1.f);
    for (int i = tid; i < 512; i += 128) {
        float v;
        if (i < 256) {
            v = g_gnsum[(i >> 6) * NGR * 64 + g * 64 + (i & 63)] * ninv;
            out[g * 256 + i] = v;
        } else {
            int c = i - 256;
            v = g_gesum[(c >> 6) * NGR * 64 + g * 64 + (c & 63)] * einv;
            out[4096 + g * 256 + c] = v;
        }
        aa[i] = v;
    }
    __syncthreads();
    {
        float s = bo1[tid];
        for (int k = 0; k < 512; ++k) s = fmaf(aa[k], Wo1[k * 128 + tid], s);
        s1[tid] = fmaxf(s, 0.f);
    }
    __syncthreads();
    {
        float s = bo2[tid];
        for (int k = 0; k < 128; ++k) s = fmaf(s1[k], Wo2[k * 128 + tid], s);
        s2[tid] = fmaxf(s, 0.f);
    }
    __syncthreads();
    if (tid < 32) {
        float s = bo3[tid];
        for (int k = 0; k < 128; ++k) s = fmaf(s2[k], Wo3[k * 32 + tid], s);
        out[8192 + g * 32 + tid] = s;
    }
}

// ---------------- launcher ----------------------------------------------------
extern "C" void kernel_launch(void* const* d_in, const int* in_sizes, int n_in,
                              void* d_out, int out_size) {
    const float* edge_attr = (const float*)d_in[1];
    const int*   eidx      = (const int*)d_in[3];
    const int*   batch     = (const int*)d_in[4];
    const int*   eb        = (const int*)d_in[5];
    const float* W1s       = (const float*)d_in[6];
    const float* b1s       = (const float*)d_in[7];
    const float* W2s       = (const float*)d_in[8];
    const float* b2s       = (const float*)d_in[9];
    const float* Wo1       = (const float*)d_in[10];
    const float* bo1       = (const float*)d_in[11];
    const float* Wo2       = (const float*)d_in[12];
    const float* bo2       = (const float*)d_in[13];
    const float* Wo3       = (const float*)d_in[14];
    const float* bo3       = (const float*)d_in[15];
    float* out = (float*)d_out;

    cudaFuncSetAttribute((const void*)k_mlp,
                         cudaFuncAttributeMaxDynamicSharedMemorySize,
                         SMEM_MLP_BYTES);

    k_init<<<2048, 256>>>();
    k_wprep<<<(NLAY * 128 * 64 + NLAY * 64 * 64 + 255) / 256, 256>>>(W1s, W2s);
    k_node_cnt<<<(N_CNT + 255) / 256, 256>>>(batch);
    k_pool0<<<E_CNT / 64, 256>>>(edge_attr, eidx, eb);
    k_finalize<<<N_CNT / 16, 256>>>(0, batch);

    for (int l = 0; l < NLAY; ++l) {
        k_hw<<<(N_CNT + 127) / 128, 256>>>(b1s + l * 128, l);
        k_mlp<<<E_CNT / TE, 128, SMEM_MLP_BYTES>>>(
            edge_attr, eidx, eb, b2s + l * 64, l);
        k_finalize<<<N_CNT / 16, 256>>>(l + 1, batch);
    }

    k_head<<<NGR, 128>>>(Wo1, bo1, Wo2, bo2, Wo3, bo3, out);
}